// round 1
// baseline (speedup 1.0000x reference)
#include <cuda_runtime.h>

#define BATCH 16
#define HEADS 8
#define BH    128           // BATCH*HEADS
#define LQ    4096
#define SK    4096
#define DIM   64
#define UU    45            // FACTOR * ceil(ln(4096)) = 5*9
#define NSPLIT 8            // split-K for P@V
#define VSPLIT 4            // split for V row-sum
#define SCALE 0.125f        // 1/sqrt(64)

// ---------------- scratch (device globals; no allocation) ----------------
__device__ float g_M[BH * LQ];                       // 2 MB
__device__ int   g_topidx[BH * UU];
__device__ float g_Ksamp[BH * UU * DIM];             // 1.5 MB
__device__ float g_Qred[BH * UU * DIM];              // 1.5 MB
__device__ float g_Vpart[BH * VSPLIT * DIM];
__device__ float g_rowsum[BH * UU];
__device__ float g_P[(size_t)BH * UU * SK];          // 94 MB (scores -> probs)
__device__ float g_ctx[BH * NSPLIT * UU * DIM];      // 9.4 MB

// ---------------- K0: gather sampled keys ----------------
__global__ void k_gather_ksamp(const float* __restrict__ keys,
                               const int* __restrict__ sidx) {
    int bh = blockIdx.x;
    for (int i = threadIdx.x; i < UU * DIM; i += blockDim.x) {
        int u = i >> 6, d = i & 63;
        int s = sidx[u];
        g_Ksamp[(bh * UU + u) * DIM + d] = keys[((size_t)bh * SK + s) * DIM + d];
    }
}

// ---------------- K1: M[b,h,l] = max_k(Q.Ks) - sum_k(Q.Ks)/S ----------------
// 64 query rows x 45 sampled keys per block, shared-mem tiled fp32 GEMM.
__global__ void k_compute_M(const float* __restrict__ q) {
    __shared__ float2 Qs[64][33];   // 64 rows x 64 dims (padded)
    __shared__ float2 Ks[48][33];   // 45 keys padded to 48
    __shared__ float  sc[64][49];   // dot results
    int bh = blockIdx.x;
    int l0 = blockIdx.y * 64;
    int tid = threadIdx.x;

    const float* qb = q + ((size_t)bh * LQ + l0) * DIM;
    float* Qsf = (float*)Qs;                       // row stride 66 floats
    for (int i = tid; i < 64 * 64; i += 256) {
        int r = i >> 6, d = i & 63;
        Qsf[r * 66 + d] = qb[i];
    }
    float* Ksf = (float*)Ks;
    for (int i = tid; i < 48 * 64; i += 256) {
        int k = i >> 6, d = i & 63;
        Ksf[k * 66 + d] = (k < UU) ? g_Ksamp[(bh * UU + k) * DIM + d] : 0.f;
    }
    __syncthreads();

    int rg = tid & 15;    // 16 row-groups x 4 rows
    int kg = tid >> 4;    // 16 key-groups x 3 keys
    float2 acc[4][3];
#pragma unroll
    for (int i = 0; i < 4; i++)
#pragma unroll
        for (int j = 0; j < 3; j++) acc[i][j] = make_float2(0.f, 0.f);

#pragma unroll 8
    for (int d2 = 0; d2 < 32; d2++) {
        float2 qv[4], kv[3];
#pragma unroll
        for (int i = 0; i < 4; i++) qv[i] = Qs[rg * 4 + i][d2];
#pragma unroll
        for (int j = 0; j < 3; j++) kv[j] = Ks[kg * 3 + j][d2];
#pragma unroll
        for (int i = 0; i < 4; i++)
#pragma unroll
            for (int j = 0; j < 3; j++) {
                acc[i][j].x += qv[i].x * kv[j].x;
                acc[i][j].y += qv[i].y * kv[j].y;
            }
    }
#pragma unroll
    for (int i = 0; i < 4; i++)
#pragma unroll
        for (int j = 0; j < 3; j++) {
            int k = kg * 3 + j;
            if (k < UU) sc[rg * 4 + i][k] = acc[i][j].x + acc[i][j].y;
        }
    __syncthreads();

    if (tid < 64) {
        float mx = -1e30f, sm = 0.f;
#pragma unroll 5
        for (int k = 0; k < UU; k++) {
            float v = sc[tid][k];
            mx = fmaxf(mx, v);
            sm += v;
        }
        g_M[bh * LQ + l0 + tid] = mx - sm * (1.0f / SK);
    }
}

// ---------------- K2: top-45 of M per (b,h) + gather Q_reduce ----------------
__global__ void k_topk(const float* __restrict__ q) {
    __shared__ float sm[LQ];
    __shared__ float rv[256];
    __shared__ int   ri[256];
    __shared__ int   sidx[UU];
    int bh = blockIdx.x, tid = threadIdx.x;

    for (int i = tid; i < LQ; i += 256) sm[i] = g_M[bh * LQ + i];
    __syncthreads();

    for (int it = 0; it < UU; it++) {
        float bv = -1e30f; int bi = LQ;
        for (int i = tid; i < LQ; i += 256) {
            float v = sm[i];
            if (v > bv) { bv = v; bi = i; }
        }
        rv[tid] = bv; ri[tid] = bi;
        __syncthreads();
        for (int off = 128; off > 0; off >>= 1) {
            if (tid < off) {
                float ov = rv[tid + off]; int oi = ri[tid + off];
                if (ov > rv[tid] || (ov == rv[tid] && oi < ri[tid])) {
                    rv[tid] = ov; ri[tid] = oi;
                }
            }
            __syncthreads();
        }
        if (tid == 0) { sidx[it] = ri[0]; sm[ri[0]] = -1e30f; }
        __syncthreads();
    }

    for (int i = tid; i < UU; i += 256) g_topidx[bh * UU + i] = sidx[i];
    for (int i = tid; i < UU * DIM; i += 256) {
        int u = i >> 6, d = i & 63;
        g_Qred[(bh * UU + u) * DIM + d] =
            q[((size_t)bh * LQ + sidx[u]) * DIM + d];
    }
}

// ---------------- K3: partial V row-sums ----------------
__global__ void k_vsum(const float* __restrict__ v) {
    __shared__ float2 red[8][33];
    int bh = blockIdx.x, sp = blockIdx.y, tid = threadIdx.x;
    int d2 = tid & 31, st = tid >> 5;     // 8 stripes x 128 s each
    const float2* vb =
        (const float2*)(v + ((size_t)bh * SK + (size_t)sp * 1024 + st * 128) * DIM);
    float2 a = make_float2(0.f, 0.f);
#pragma unroll 8
    for (int s = 0; s < 128; s++) {
        float2 x = vb[s * 32 + d2];
        a.x += x.x; a.y += x.y;
    }
    red[st][d2] = a;
    __syncthreads();
    if (tid < 32) {
        float2 s = make_float2(0.f, 0.f);
#pragma unroll
        for (int k = 0; k < 8; k++) { s.x += red[k][tid].x; s.y += red[k][tid].y; }
        *(float2*)&g_Vpart[(bh * VSPLIT + sp) * DIM + 2 * tid] = s;
    }
}

// ---------------- K4: broadcast V_sum into entire output ----------------
__global__ void k_fill(float* __restrict__ out) {
    __shared__ float sv[64];
    int bh = blockIdx.x, ry = blockIdx.y, tid = threadIdx.x;
    if (tid < 64) {
        float s = 0.f;
#pragma unroll
        for (int sp = 0; sp < VSPLIT; sp++) s += g_Vpart[(bh * VSPLIT + sp) * DIM + tid];
        sv[tid] = s;
    }
    __syncthreads();
    float4* o4 = (float4*)(out + ((size_t)bh * LQ + (size_t)ry * 128) * DIM);
    const float4* s4 = (const float4*)sv;
    float4 val = s4[tid & 15];            // (256 % 16)==0 -> constant per thread
    for (int i = tid; i < 128 * 16; i += 256) o4[i] = val;
}

// ---------------- K5: scores = scale * Qred @ K^T (45 x 4096 per bh) ----------------
__global__ void k_scores(const float* __restrict__ keys) {
    __shared__ float2 Qr[48][33];
    __shared__ float2 Kt[128][33];
    int bh = blockIdx.x;
    int s0 = blockIdx.y * 128;
    int tid = threadIdx.x;

    float* Qrf = (float*)Qr;
    for (int i = tid; i < 48 * 64; i += 256) {
        int r = i >> 6, d = i & 63;
        Qrf[r * 66 + d] = (r < UU) ? g_Qred[(bh * UU + r) * DIM + d] : 0.f;
    }
    float* Ktf = (float*)Kt;
    const float* kb = keys + ((size_t)bh * SK + s0) * DIM;
    for (int i = tid; i < 128 * 64; i += 256) {
        int k = i >> 6, d = i & 63;
        Ktf[k * 66 + d] = kb[i];
    }
    __syncthreads();

    int rg = tid & 15;    // 16 x 3 rows
    int kg = tid >> 4;    // 16 x 8 keys
    float2 acc[3][8];
#pragma unroll
    for (int i = 0; i < 3; i++)
#pragma unroll
        for (int j = 0; j < 8; j++) acc[i][j] = make_float2(0.f, 0.f);

#pragma unroll 4
    for (int d2 = 0; d2 < 32; d2++) {
        float2 qv[3], kv[8];
#pragma unroll
        for (int i = 0; i < 3; i++) qv[i] = Qr[rg * 3 + i][d2];
#pragma unroll
        for (int j = 0; j < 8; j++) kv[j] = Kt[kg * 8 + j][d2];
#pragma unroll
        for (int i = 0; i < 3; i++)
#pragma unroll
            for (int j = 0; j < 8; j++) {
                acc[i][j].x += qv[i].x * kv[j].x;
                acc[i][j].y += qv[i].y * kv[j].y;
            }
    }
    __syncthreads();

    float* Sout = (float*)Kt;             // reuse (needs 48*129 = 6192 floats)
#pragma unroll
    for (int i = 0; i < 3; i++)
#pragma unroll
        for (int j = 0; j < 8; j++)
            Sout[(rg * 3 + i) * 129 + kg * 8 + j] =
                (acc[i][j].x + acc[i][j].y) * SCALE;
    __syncthreads();

    for (int i = tid; i < UU * 128; i += 256) {
        int r = i >> 7, c = i & 127;
        g_P[((size_t)bh * UU + r) * SK + s0 + c] = Sout[r * 129 + c];
    }
}

// ---------------- K6: row softmax (in place, unnormalized exp + row sums) ----------------
__global__ void k_softmax() {
    __shared__ float red[256];
    int bh = blockIdx.x, u = blockIdx.y, tid = threadIdx.x;
    float4* row = (float4*)(g_P + ((size_t)bh * UU + u) * SK);

    float4 v[4];
    float mx = -1e30f;
#pragma unroll
    for (int j = 0; j < 4; j++) {
        v[j] = row[tid + j * 256];
        mx = fmaxf(mx, fmaxf(fmaxf(v[j].x, v[j].y), fmaxf(v[j].z, v[j].w)));
    }
    red[tid] = mx;
    __syncthreads();
    for (int off = 128; off > 0; off >>= 1) {
        if (tid < off) red[tid] = fmaxf(red[tid], red[tid + off]);
        __syncthreads();
    }
    mx = red[0];
    __syncthreads();

    float sm = 0.f;
#pragma unroll
    for (int j = 0; j < 4; j++) {
        v[j].x = __expf(v[j].x - mx);
        v[j].y = __expf(v[j].y - mx);
        v[j].z = __expf(v[j].z - mx);
        v[j].w = __expf(v[j].w - mx);
        sm += v[j].x + v[j].y + v[j].z + v[j].w;
        row[tid + j * 256] = v[j];
    }
    red[tid] = sm;
    __syncthreads();
    for (int off = 128; off > 0; off >>= 1) {
        if (tid < off) red[tid] += red[tid + off];
        __syncthreads();
    }
    if (tid == 0) g_rowsum[bh * UU + u] = red[0];
}

// ---------------- K7: ctx partials = P @ V (split over S) ----------------
__global__ void k_ctx(const float* __restrict__ v) {
    __shared__ float  Pt[48 * 65];
    __shared__ float2 Vt[64][33];
    int bh = blockIdx.x, sp = blockIdx.y, tid = threadIdx.x;
    int ug = tid & 15;   // 16 x 3 u-rows
    int dg = tid >> 4;   // 16 x 4 dims (2 float2)
    float2 acc[3][2];
#pragma unroll
    for (int i = 0; i < 3; i++)
#pragma unroll
        for (int dd = 0; dd < 2; dd++) acc[i][dd] = make_float2(0.f, 0.f);

    for (int t = 0; t < 8; t++) {
        int sb = sp * 512 + t * 64;
        for (int i = tid; i < 48 * 64; i += 256) {
            int r = i >> 6, c = i & 63;
            Pt[r * 65 + c] = (r < UU) ? g_P[((size_t)bh * UU + r) * SK + sb + c] : 0.f;
        }
        float* Vtf = (float*)Vt;
        const float* vb = v + ((size_t)bh * SK + sb) * DIM;
        for (int i = tid; i < 64 * 64; i += 256) {
            int s = i >> 6, d = i & 63;
            Vtf[s * 66 + d] = vb[i];
        }
        __syncthreads();

#pragma unroll 8
        for (int s = 0; s < 64; s++) {
            float p[3]; float2 vv[2];
#pragma unroll
            for (int i = 0; i < 3; i++) p[i] = Pt[(ug * 3 + i) * 65 + s];
#pragma unroll
            for (int dd = 0; dd < 2; dd++) vv[dd] = Vt[s][dg * 2 + dd];
#pragma unroll
            for (int i = 0; i < 3; i++)
#pragma unroll
                for (int dd = 0; dd < 2; dd++) {
                    acc[i][dd].x += p[i] * vv[dd].x;
                    acc[i][dd].y += p[i] * vv[dd].y;
                }
        }
        __syncthreads();
    }

#pragma unroll
    for (int i = 0; i < 3; i++) {
        int u = ug * 3 + i;
        if (u < UU) {
#pragma unroll
            for (int dd = 0; dd < 2; dd++) {
                int d = dg * 4 + dd * 2;
                int base = ((bh * NSPLIT + sp) * UU + u) * DIM + d;
                g_ctx[base]     = acc[i][dd].x;
                g_ctx[base + 1] = acc[i][dd].y;
            }
        }
    }
}

// ---------------- K8: combine partials, normalize, scatter into output ----------------
__global__ void k_combine(float* __restrict__ out) {
    int bh = blockIdx.x, tid = threadIdx.x;
    for (int i = tid; i < UU * DIM; i += 256) {
        int u = i >> 6, d = i & 63;
        float s = 0.f;
#pragma unroll
        for (int sp = 0; sp < NSPLIT; sp++)
            s += g_ctx[((bh * NSPLIT + sp) * UU + u) * DIM + d];
        int l = g_topidx[bh * UU + u];
        out[((size_t)bh * LQ + l) * DIM + d] = s / g_rowsum[bh * UU + u];
    }
}

// ---------------- launch ----------------
extern "C" void kernel_launch(void* const* d_in, const int* in_sizes, int n_in,
                              void* d_out, int out_size) {
    const float* q    = (const float*)d_in[0];
    const float* keys = (const float*)d_in[1];
    const float* vals = (const float*)d_in[2];
    const int*   sidx = (const int*)d_in[3];
    float* out = (float*)d_out;

    k_gather_ksamp<<<BH, 256>>>(keys, sidx);
    k_compute_M<<<dim3(BH, LQ / 64), 256>>>(q);
    k_topk<<<BH, 256>>>(q);
    k_vsum<<<dim3(BH, VSPLIT), 256>>>(vals);
    k_fill<<<dim3(BH, LQ / 128), 256>>>(out);
    k_scores<<<dim3(BH, SK / 128), 256>>>(keys);
    k_softmax<<<dim3(BH, UU), 256>>>();
    k_ctx<<<dim3(BH, NSPLIT), 256>>>(vals);
    k_combine<<<BH, 256>>>(out);
}

// round 2
// speedup vs baseline: 1.8206x; 1.8206x over previous
#include <cuda_runtime.h>

#define BH   128
#define LQ   4096
#define SK   4096
#define DIM  64
#define UU   45
#define NS   8
#define SCALE 0.125f

// ---------------- scratch ----------------
__device__ float  g_M[BH * LQ];
__device__ int    g_topidx[BH * UU];
__device__ float  g_Ksamp[BH * UU * DIM];
__device__ float  g_Qred[BH * UU * DIM];
__device__ float  g_Vpart[BH * 8 * DIM];
__device__ float  g_actx[BH * 16 * UU * DIM];    // 16 partials (8 splits x 2 key-halves)
__device__ float2 g_aml[BH * 16 * UU];           // per-partial (max, sum)

// ---------------- helpers ----------------
__device__ __forceinline__ unsigned f2tf(float f) {
    unsigned u; asm("cvt.rna.tf32.f32 %0, %1;" : "=r"(u) : "f"(f)); return u;
}
__device__ __forceinline__ void mma8(float* d, const unsigned* a, unsigned b0, unsigned b1) {
    asm volatile("mma.sync.aligned.m16n8k8.row.col.f32.tf32.tf32.f32 "
                 "{%0,%1,%2,%3}, {%4,%5,%6,%7}, {%8,%9}, {%0,%1,%2,%3};"
                 : "+f"(d[0]), "+f"(d[1]), "+f"(d[2]), "+f"(d[3])
                 : "r"(a[0]), "r"(a[1]), "r"(a[2]), "r"(a[3]), "r"(b0), "r"(b1));
}
__device__ __forceinline__ float qmaxf(float v) {
    v = fmaxf(v, __shfl_xor_sync(0xffffffffu, v, 1));
    v = fmaxf(v, __shfl_xor_sync(0xffffffffu, v, 2));
    return v;
}
__device__ __forceinline__ float qsumf(float v) {
    v += __shfl_xor_sync(0xffffffffu, v, 1);
    v += __shfl_xor_sync(0xffffffffu, v, 2);
    return v;
}

// ---------------- K0: gather sampled keys ----------------
__global__ void k_gather_ksamp(const float* __restrict__ keys,
                               const int* __restrict__ sidx) {
    int bh = blockIdx.x;
    for (int i = threadIdx.x; i < UU * DIM; i += blockDim.x) {
        int u = i >> 6, d = i & 63;
        int s = sidx[u];
        g_Ksamp[(bh * UU + u) * DIM + d] = keys[((size_t)bh * SK + s) * DIM + d];
    }
}

// ---------------- K1: M via 3xTF32 tensor GEMM (fp32-accurate) ----------------
// Block: 64 q-rows x 45 sampled keys. Warps: rg=w&3 (16-row strip), kh=w>>2 (dim half).
__global__ __launch_bounds__(256) void k_M(const float* __restrict__ q) {
    __shared__ float Qs[64 * 68];
    __shared__ float Ks[48 * 68];
    __shared__ float Sr[64 * 52];
    int bh = blockIdx.x, l0 = blockIdx.y * 64;
    int tid = threadIdx.x, w = tid >> 5, lane = tid & 31;
    int rg = w & 3, kh = w >> 2, lq = lane >> 2, lr = lane & 3;

    const float* qb = q + ((size_t)bh * LQ + l0) * DIM;
    for (int i = tid; i < 64 * 64; i += 256) Qs[(i >> 6) * 68 + (i & 63)] = qb[i];
    for (int i = tid; i < 48 * 64; i += 256) {
        int r = i >> 6, d = i & 63;
        Ks[r * 68 + d] = (r < UU) ? g_Ksamp[(bh * UU + r) * DIM + d] : 0.f;
    }
    __syncthreads();

    float C[6][4];
#pragma unroll
    for (int n = 0; n < 6; n++) { C[n][0] = C[n][1] = C[n][2] = C[n][3] = 0.f; }

#pragma unroll
    for (int ks = 0; ks < 4; ks++) {
        int c0 = 32 * kh + 8 * ks + lr;
        float f0 = Qs[(16 * rg + lq) * 68 + c0];
        float f1 = Qs[(16 * rg + lq + 8) * 68 + c0];
        float f2 = Qs[(16 * rg + lq) * 68 + c0 + 4];
        float f3 = Qs[(16 * rg + lq + 8) * 68 + c0 + 4];
        unsigned ah[4], al[4];
        ah[0] = __float_as_uint(f0) & 0xffffe000u; al[0] = f2tf(f0 - __uint_as_float(ah[0]));
        ah[1] = __float_as_uint(f1) & 0xffffe000u; al[1] = f2tf(f1 - __uint_as_float(ah[1]));
        ah[2] = __float_as_uint(f2) & 0xffffe000u; al[2] = f2tf(f2 - __uint_as_float(ah[2]));
        ah[3] = __float_as_uint(f3) & 0xffffe000u; al[3] = f2tf(f3 - __uint_as_float(ah[3]));
#pragma unroll
        for (int nt = 0; nt < 6; nt++) {
            float g0 = Ks[(8 * nt + lq) * 68 + c0];
            float g1 = Ks[(8 * nt + lq) * 68 + c0 + 4];
            unsigned bh0 = __float_as_uint(g0) & 0xffffe000u;
            unsigned bh1 = __float_as_uint(g1) & 0xffffe000u;
            unsigned bl0 = f2tf(g0 - __uint_as_float(bh0));
            unsigned bl1 = f2tf(g1 - __uint_as_float(bh1));
            mma8(C[nt], ah, bh0, bh1);   // hi*hi
            mma8(C[nt], ah, bl0, bl1);   // hi*lo
            mma8(C[nt], al, bh0, bh1);   // lo*hi
        }
    }

    if (kh == 1) {
#pragma unroll
        for (int nt = 0; nt < 6; nt++) {
            *(float2*)&Sr[(16 * rg + lq) * 52 + 8 * nt + 2 * lr]     = make_float2(C[nt][0], C[nt][1]);
            *(float2*)&Sr[(16 * rg + lq + 8) * 52 + 8 * nt + 2 * lr] = make_float2(C[nt][2], C[nt][3]);
        }
    }
    __syncthreads();
    if (kh == 0) {
        float mx0 = -1e30f, mx1 = -1e30f, sm0 = 0.f, sm1 = 0.f;
#pragma unroll
        for (int nt = 0; nt < 6; nt++) {
            float2 p0 = *(float2*)&Sr[(16 * rg + lq) * 52 + 8 * nt + 2 * lr];
            float2 p1 = *(float2*)&Sr[(16 * rg + lq + 8) * 52 + 8 * nt + 2 * lr];
            float v00 = C[nt][0] + p0.x, v01 = C[nt][1] + p0.y;
            float v10 = C[nt][2] + p1.x, v11 = C[nt][3] + p1.y;
            int col = 8 * nt + 2 * lr;
            sm0 += v00 + v01; sm1 += v10 + v11;   // pad cols are exact zeros
            if (col < UU)     { mx0 = fmaxf(mx0, v00); mx1 = fmaxf(mx1, v10); }
            if (col + 1 < UU) { mx0 = fmaxf(mx0, v01); mx1 = fmaxf(mx1, v11); }
        }
        mx0 = qmaxf(mx0); mx1 = qmaxf(mx1); sm0 = qsumf(sm0); sm1 = qsumf(sm1);
        if (lr == 0) {
            g_M[bh * LQ + l0 + 16 * rg + lq]     = mx0 - sm0 * (1.0f / SK);
            g_M[bh * LQ + l0 + 16 * rg + lq + 8] = mx1 - sm1 * (1.0f / SK);
        }
    }
}

// ---------------- K2: top-45 of M per (b,h) + gather Q_reduce ----------------
__global__ void k_topk(const float* __restrict__ q) {
    __shared__ float sm[LQ];
    __shared__ float rv[256];
    __shared__ int   ri[256];
    __shared__ int   sidx[UU];
    int bh = blockIdx.x, tid = threadIdx.x;

    for (int i = tid; i < LQ; i += 256) sm[i] = g_M[bh * LQ + i];
    __syncthreads();

    for (int it = 0; it < UU; it++) {
        float bv = -1e30f; int bi = LQ;
        for (int i = tid; i < LQ; i += 256) {
            float v = sm[i];
            if (v > bv) { bv = v; bi = i; }
        }
        rv[tid] = bv; ri[tid] = bi;
        __syncthreads();
        for (int off = 128; off > 0; off >>= 1) {
            if (tid < off) {
                float ov = rv[tid + off]; int oi = ri[tid + off];
                if (ov > rv[tid] || (ov == rv[tid] && oi < ri[tid])) {
                    rv[tid] = ov; ri[tid] = oi;
                }
            }
            __syncthreads();
        }
        if (tid == 0) { sidx[it] = ri[0]; sm[ri[0]] = -1e30f; }
        __syncthreads();
    }

    for (int i = tid; i < UU; i += 256) g_topidx[bh * UU + i] = sidx[i];
    for (int i = tid; i < UU * DIM; i += 256) {
        int u = i >> 6, d = i & 63;
        g_Qred[(bh * UU + u) * DIM + d] = q[((size_t)bh * LQ + sidx[u]) * DIM + d];
    }
}

// ---------------- K3: partial V row-sums (float4, 8-way split) ----------------
__global__ void k_vsum(const float* __restrict__ v) {
    __shared__ float4 red[16][17];
    int bh = blockIdx.x, sp = blockIdx.y, tid = threadIdx.x;
    int d4 = tid & 15, st = tid >> 4;
    const float4* vb = (const float4*)(v + ((size_t)bh * SK + sp * 512 + st * 32) * DIM);
    float4 a = make_float4(0.f, 0.f, 0.f, 0.f);
#pragma unroll 8
    for (int s = 0; s < 32; s++) {
        float4 x = vb[s * 16 + d4];
        a.x += x.x; a.y += x.y; a.z += x.z; a.w += x.w;
    }
    red[st][d4] = a;
    __syncthreads();
    if (tid < 16) {
        float4 s = red[0][tid];
#pragma unroll
        for (int k = 1; k < 16; k++) {
            float4 x = red[k][tid];
            s.x += x.x; s.y += x.y; s.z += x.z; s.w += x.w;
        }
        ((float4*)&g_Vpart[(bh * 8 + sp) * DIM])[tid] = s;
    }
}

// ---------------- K4: broadcast V_sum into entire output ----------------
__global__ void k_fill(float* __restrict__ out) {
    __shared__ float sv[64];
    int bh = blockIdx.x, ry = blockIdx.y, tid = threadIdx.x;
    if (tid < 64) {
        float s = 0.f;
#pragma unroll
        for (int sp = 0; sp < 8; sp++) s += g_Vpart[(bh * 8 + sp) * DIM + tid];
        sv[tid] = s;
    }
    __syncthreads();
    float4* o4 = (float4*)(out + ((size_t)bh * LQ + (size_t)ry * 128) * DIM);
    float4 val = ((const float4*)sv)[tid & 15];
    for (int i = tid; i < 128 * 16; i += 256) o4[i] = val;
}

// ---------------- K5: fused flash attention over Qred (tf32 mma, split-S) ----------------
// grid (BH, NS); each block: 45(pad 64) queries x 512 keys in 4 tiles of 128.
// Warps: rg=w&3 (16-row strip), kh=w>>2 (key half of the 128-key tile).
__global__ __launch_bounds__(256, 2) void k_attn(const float* __restrict__ K,
                                                 const float* __restrict__ V) {
    extern __shared__ float smf[];
    float* Qs = smf;                 // 64 x 68
    float* KP = smf + 64 * 68;       // 128 x 68 (K tile, reused as P)
    float* Vt = KP + 128 * 68;       // 128 x 72
    int bh = blockIdx.x, sp = blockIdx.y;
    int tid = threadIdx.x, w = tid >> 5, lane = tid & 31;
    int rg = w & 3, kh = w >> 2, lq = lane >> 2, lr = lane & 3;

    for (int i = tid; i < 64 * 64; i += 256) {
        int r = i >> 6, d = i & 63;
        Qs[r * 68 + d] = (r < UU) ? g_Qred[(bh * UU + r) * DIM + d] : 0.f;
    }
    __syncthreads();

    unsigned aq[8][4];
#pragma unroll
    for (int ks = 0; ks < 8; ks++) {
        aq[ks][0] = f2tf(Qs[(16 * rg + lq) * 68 + 8 * ks + lr]);
        aq[ks][1] = f2tf(Qs[(16 * rg + lq + 8) * 68 + 8 * ks + lr]);
        aq[ks][2] = f2tf(Qs[(16 * rg + lq) * 68 + 8 * ks + lr + 4]);
        aq[ks][3] = f2tf(Qs[(16 * rg + lq + 8) * 68 + 8 * ks + lr + 4]);
    }

    float O[8][4];
#pragma unroll
    for (int n = 0; n < 8; n++) { O[n][0] = O[n][1] = O[n][2] = O[n][3] = 0.f; }
    float m0 = -1e30f, m1 = -1e30f, l0a = 0.f, l1a = 0.f;

    for (int t = 0; t < 4; t++) {
        __syncthreads();                       // prev-tile P/V reads done
        int s0 = sp * 512 + t * 128;
        const float4* kb = (const float4*)(K + ((size_t)bh * SK + s0) * DIM);
        const float4* vb = (const float4*)(V + ((size_t)bh * SK + s0) * DIM);
        for (int i = tid; i < 128 * 16; i += 256) {
            int r = i >> 4, c4 = i & 15;
            *(float4*)&KP[r * 68 + 4 * c4] = kb[i];
            *(float4*)&Vt[r * 72 + 4 * c4] = vb[i];
        }
        __syncthreads();

        // S = Q @ K^T (warp: 16 rows x 64 keys of its half)
        float C[8][4];
#pragma unroll
        for (int n = 0; n < 8; n++) { C[n][0] = C[n][1] = C[n][2] = C[n][3] = 0.f; }
#pragma unroll
        for (int ks = 0; ks < 8; ks++) {
#pragma unroll
            for (int nt = 0; nt < 8; nt++) {
                unsigned b0 = f2tf(KP[(64 * kh + 8 * nt + lq) * 68 + 8 * ks + lr]);
                unsigned b1 = f2tf(KP[(64 * kh + 8 * nt + lq) * 68 + 8 * ks + lr + 4]);
                mma8(C[nt], aq[ks], b0, b1);
            }
        }

        // online softmax (rows lq and lq+8)
        float tm0 = -1e30f, tm1 = -1e30f;
#pragma unroll
        for (int nt = 0; nt < 8; nt++) {
            C[nt][0] *= SCALE; C[nt][1] *= SCALE; C[nt][2] *= SCALE; C[nt][3] *= SCALE;
            tm0 = fmaxf(tm0, fmaxf(C[nt][0], C[nt][1]));
            tm1 = fmaxf(tm1, fmaxf(C[nt][2], C[nt][3]));
        }
        tm0 = qmaxf(tm0); tm1 = qmaxf(tm1);
        float nm0 = fmaxf(m0, tm0), nm1 = fmaxf(m1, tm1);
        float f0 = __expf(m0 - nm0), f1 = __expf(m1 - nm1);
        float rs0 = 0.f, rs1 = 0.f;
#pragma unroll
        for (int nt = 0; nt < 8; nt++) {
            C[nt][0] = __expf(C[nt][0] - nm0); C[nt][1] = __expf(C[nt][1] - nm0);
            C[nt][2] = __expf(C[nt][2] - nm1); C[nt][3] = __expf(C[nt][3] - nm1);
            rs0 += C[nt][0] + C[nt][1]; rs1 += C[nt][2] + C[nt][3];
            O[nt][0] *= f0; O[nt][1] *= f0; O[nt][2] *= f1; O[nt][3] *= f1;
        }
        rs0 = qsumf(rs0); rs1 = qsumf(rs1);
        l0a = l0a * f0 + rs0; l1a = l1a * f1 + rs1;
        m0 = nm0; m1 = nm1;

        __syncthreads();                       // all warps done reading K
        // P -> smem (warp-private 16x64 strip at rows 16w)
#pragma unroll
        for (int nt = 0; nt < 8; nt++) {
            *(float2*)&KP[(16 * w + lq) * 68 + 8 * nt + 2 * lr]     = make_float2(C[nt][0], C[nt][1]);
            *(float2*)&KP[(16 * w + lq + 8) * 68 + 8 * nt + 2 * lr] = make_float2(C[nt][2], C[nt][3]);
        }
        __syncthreads();

        // O += P @ V
#pragma unroll
        for (int ks = 0; ks < 8; ks++) {
            unsigned ap[4];
            ap[0] = f2tf(KP[(16 * w + lq) * 68 + 8 * ks + lr]);
            ap[1] = f2tf(KP[(16 * w + lq + 8) * 68 + 8 * ks + lr]);
            ap[2] = f2tf(KP[(16 * w + lq) * 68 + 8 * ks + lr + 4]);
            ap[3] = f2tf(KP[(16 * w + lq + 8) * 68 + 8 * ks + lr + 4]);
#pragma unroll
            for (int nt = 0; nt < 8; nt++) {
                unsigned b0 = f2tf(Vt[(64 * kh + 8 * ks + lr) * 72 + 8 * nt + lq]);
                unsigned b1 = f2tf(Vt[(64 * kh + 8 * ks + lr + 4) * 72 + 8 * nt + lq]);
                mma8(O[nt], ap, b0, b1);
            }
        }
    }

    // store partial (O, m, l); part index = 2*sp + kh
    int p = sp * 2 + kh;
    int r0 = 16 * rg + lq, r1 = r0 + 8;
    if (r0 < UU) {
        float* dst = &g_actx[((bh * 16 + p) * UU + r0) * DIM];
#pragma unroll
        for (int nt = 0; nt < 8; nt++)
            *(float2*)&dst[8 * nt + 2 * lr] = make_float2(O[nt][0], O[nt][1]);
        if (lr == 0) g_aml[(bh * 16 + p) * UU + r0] = make_float2(m0, l0a);
    }
    if (r1 < UU) {
        float* dst = &g_actx[((bh * 16 + p) * UU + r1) * DIM];
#pragma unroll
        for (int nt = 0; nt < 8; nt++)
            *(float2*)&dst[8 * nt + 2 * lr] = make_float2(O[nt][2], O[nt][3]);
        if (lr == 0) g_aml[(bh * 16 + p) * UU + r1] = make_float2(m1, l1a);
    }
}

// ---------------- K6: merge 16 partials, normalize, scatter ----------------
__global__ void k_combine(float* __restrict__ out) {
    __shared__ float wgt[UU * 16];
    __shared__ float Lr[UU];
    __shared__ int   idx[UU];
    int bh = blockIdx.x, tid = threadIdx.x;
    if (tid < UU) {
        float2 ml[16]; float mg = -1e30f;
#pragma unroll
        for (int p = 0; p < 16; p++) {
            ml[p] = g_aml[(bh * 16 + p) * UU + tid];
            mg = fmaxf(mg, ml[p].x);
        }
        float L = 0.f;
#pragma unroll
        for (int p = 0; p < 16; p++) {
            float wv = __expf(ml[p].x - mg);
            wgt[tid * 16 + p] = wv;
            L += wv * ml[p].y;
        }
        Lr[tid] = L;
        idx[tid] = g_topidx[bh * UU + tid];
    }
    __syncthreads();
    for (int i = tid; i < UU * DIM; i += 256) {
        int u = i >> 6, d = i & 63;
        float s = 0.f;
#pragma unroll
        for (int p = 0; p < 16; p++)
            s += wgt[u * 16 + p] * g_actx[((bh * 16 + p) * UU + u) * DIM + d];
        out[((size_t)bh * LQ + idx[u]) * DIM + d] = s / Lr[u];
    }
}

// ---------------- launch ----------------
#define ATTN_SMEM ((64 * 68 + 128 * 68 + 128 * 72) * 4)

extern "C" void kernel_launch(void* const* d_in, const int* in_sizes, int n_in,
                              void* d_out, int out_size) {
    const float* q    = (const float*)d_in[0];
    const float* keys = (const float*)d_in[1];
    const float* vals = (const float*)d_in[2];
    const int*   sidx = (const int*)d_in[3];
    float* out = (float*)d_out;

    cudaFuncSetAttribute(k_attn, cudaFuncAttributeMaxDynamicSharedMemorySize, ATTN_SMEM);

    k_gather_ksamp<<<BH, 256>>>(keys, sidx);
    k_M<<<dim3(BH, LQ / 64), 256>>>(q);
    k_topk<<<BH, 256>>>(q);
    k_vsum<<<dim3(BH, 8), 256>>>(vals);
    k_fill<<<dim3(BH, LQ / 128), 256>>>(out);
    k_attn<<<dim3(BH, NS), 256, ATTN_SMEM>>>(keys, vals);
    k_combine<<<BH, 256>>>(out);
}

// round 3
// speedup vs baseline: 1.9584x; 1.0757x over previous
#include <cuda_runtime.h>

#define BH   128
#define LQ   4096
#define SK   4096
#define DIM  64
#define UU   45
#define NS   8

// col permutation pairing (c, c+4) adjacently within each 8-group
#define PCOL(c) (((c) & ~7) | (((c) & 3) << 1) | (((c) & 4) >> 2))

// ---------------- scratch ----------------
__device__ float    g_M[BH * LQ];
__device__ int      g_topidx[BH * UU];
__device__ unsigned g_KsHi[BH * 48 * DIM];       // permuted, tf32-hi
__device__ unsigned g_KsLo[BH * 48 * DIM];       // permuted, tf32-lo
__device__ float    g_Qred[BH * UU * DIM];       // tf32-valued, pre-scaled
__device__ float    g_Vpart[BH * NS * DIM];
__device__ float    g_actx[BH * 16 * UU * DIM];
__device__ float2   g_aml[BH * 16 * UU];

// ---------------- helpers ----------------
__device__ __forceinline__ unsigned f2tf(float f) {
    unsigned u; asm("cvt.rna.tf32.f32 %0, %1;" : "=r"(u) : "f"(f)); return u;
}
__device__ __forceinline__ float t32(float f) { return __uint_as_float(f2tf(f)); }
__device__ __forceinline__ void mma8(float* d, const unsigned* a, unsigned b0, unsigned b1) {
    asm volatile("mma.sync.aligned.m16n8k8.row.col.f32.tf32.tf32.f32 "
                 "{%0,%1,%2,%3}, {%4,%5,%6,%7}, {%8,%9}, {%0,%1,%2,%3};"
                 : "+f"(d[0]), "+f"(d[1]), "+f"(d[2]), "+f"(d[3])
                 : "r"(a[0]), "r"(a[1]), "r"(a[2]), "r"(a[3]), "r"(b0), "r"(b1));
}
__device__ __forceinline__ float qmaxf(float v) {
    v = fmaxf(v, __shfl_xor_sync(0xffffffffu, v, 1));
    v = fmaxf(v, __shfl_xor_sync(0xffffffffu, v, 2));
    return v;
}
__device__ __forceinline__ float qsumf(float v) {
    v += __shfl_xor_sync(0xffffffffu, v, 1);
    v += __shfl_xor_sync(0xffffffffu, v, 2);
    return v;
}

// ---------------- K0: gather sampled keys, split hi/lo, permute ----------------
__global__ void k_gather(const float* __restrict__ keys, const int* __restrict__ sidx) {
    int bh = blockIdx.x;
    for (int i = threadIdx.x; i < 48 * DIM; i += 256) {
        int u = i >> 6, d = i & 63;
        float v = (u < UU) ? keys[((size_t)bh * SK + sidx[u]) * DIM + d] : 0.f;
        unsigned hi = __float_as_uint(v) & 0xffffe000u;
        unsigned lo = f2tf(v - __uint_as_float(hi));
        g_KsHi[bh * 48 * DIM + u * DIM + PCOL(d)] = hi;
        g_KsLo[bh * 48 * DIM + u * DIM + PCOL(d)] = lo;
    }
}

// ---------------- K1: M via 3xTF32 tensor GEMM (fp32-accurate) ----------------
// 64 q-rows x 48 keys. Warps: rg=w&3 (16 rows), kh=w>>2 (24-key half, full K-dim).
__global__ __launch_bounds__(256) void k_M(const float* __restrict__ q) {
    extern __shared__ float dynsm[];
    unsigned* Qhi = (unsigned*)dynsm;          // 64*68
    unsigned* Qlo = Qhi + 64 * 68;
    unsigned* Khi = Qlo + 64 * 68;             // 48*68
    unsigned* Klo = Khi + 48 * 68;
    __shared__ float redmx[2][64], redsm[2][64];

    int bh = blockIdx.x, l0 = blockIdx.y * 64;
    int tid = threadIdx.x, w = tid >> 5, lane = tid & 31;
    int rg = w & 3, kh = w >> 2, lq = lane >> 2, lr = lane & 3;

    const float4* qb4 = (const float4*)(q + ((size_t)bh * LQ + l0) * DIM);
    for (int i = tid; i < 64 * 16; i += 256) {
        int r = i >> 4, cb = (i & 15) * 4;
        float4 f = qb4[i];
        int base = r * 68 + (cb & ~7) + ((cb & 4) >> 2);
        float vv[4] = {f.x, f.y, f.z, f.w};
#pragma unroll
        for (int j = 0; j < 4; j++) {
            unsigned hi = __float_as_uint(vv[j]) & 0xffffe000u;
            Qhi[base + 2 * j] = hi;
            Qlo[base + 2 * j] = f2tf(vv[j] - __uint_as_float(hi));
        }
    }
    for (int i = tid; i < 48 * 64; i += 256) {
        int r = i >> 6, c = i & 63;              // c = physical (permuted) position
        Khi[r * 68 + c] = g_KsHi[bh * 48 * DIM + i];
        Klo[r * 68 + c] = g_KsLo[bh * 48 * DIM + i];
    }
    __syncthreads();

    float C[3][4];
#pragma unroll
    for (int n = 0; n < 3; n++) { C[n][0] = C[n][1] = C[n][2] = C[n][3] = 0.f; }

#pragma unroll
    for (int ks = 0; ks < 8; ks++) {
        int ra = (16 * rg + lq) * 68 + 8 * ks + 2 * lr;
        uint2 h0 = *(uint2*)&Qhi[ra];
        uint2 h1 = *(uint2*)&Qhi[ra + 8 * 68];
        uint2 q0 = *(uint2*)&Qlo[ra];
        uint2 q1 = *(uint2*)&Qlo[ra + 8 * 68];
        unsigned ah[4] = {h0.x, h1.x, h0.y, h1.y};
        unsigned al[4] = {q0.x, q1.x, q0.y, q1.y};
#pragma unroll
        for (int nt = 0; nt < 3; nt++) {
            int rb = (24 * kh + 8 * nt + lq) * 68 + 8 * ks + 2 * lr;
            uint2 bhv = *(uint2*)&Khi[rb];
            uint2 blv = *(uint2*)&Klo[rb];
            mma8(C[nt], ah, bhv.x, bhv.y);   // hi*hi
            mma8(C[nt], ah, blv.x, blv.y);   // hi*lo
            mma8(C[nt], al, bhv.x, bhv.y);   // lo*hi
        }
    }

    float mx0 = -1e30f, mx1 = -1e30f, sm0 = 0.f, sm1 = 0.f;
#pragma unroll
    for (int nt = 0; nt < 3; nt++) {
        int c0 = 24 * kh + 8 * nt + 2 * lr;
        sm0 += C[nt][0] + C[nt][1];          // pad cols are exact zeros
        sm1 += C[nt][2] + C[nt][3];
        if (c0 < UU)     { mx0 = fmaxf(mx0, C[nt][0]); mx1 = fmaxf(mx1, C[nt][2]); }
        if (c0 + 1 < UU) { mx0 = fmaxf(mx0, C[nt][1]); mx1 = fmaxf(mx1, C[nt][3]); }
    }
    mx0 = qmaxf(mx0); mx1 = qmaxf(mx1); sm0 = qsumf(sm0); sm1 = qsumf(sm1);
    if (lr == 0) {
        int r0 = 16 * rg + lq;
        redmx[kh][r0] = mx0; redmx[kh][r0 + 8] = mx1;
        redsm[kh][r0] = sm0; redsm[kh][r0 + 8] = sm1;
    }
    __syncthreads();
    if (tid < 64)
        g_M[bh * LQ + l0 + tid] = fmaxf(redmx[0][tid], redmx[1][tid]) -
                                  (redsm[0][tid] + redsm[1][tid]) * (1.0f / SK);
}

// ---------------- K2: top-45 + gather/convert Q_reduce ----------------
__global__ __launch_bounds__(256) void k_topk(const float* __restrict__ q) {
    __shared__ float sm[LQ];
    __shared__ float wv[8];
    __shared__ int   wi[8];
    __shared__ int   sidx[UU];
    int bh = blockIdx.x, tid = threadIdx.x, w = tid >> 5, lane = tid & 31;

    for (int i = tid; i < LQ; i += 256) sm[i] = g_M[bh * LQ + i];
    __syncthreads();

    for (int it = 0; it < UU; it++) {
        float bv = -1e30f; int bi = 1 << 30;
#pragma unroll
        for (int j = 0; j < 16; j++) {
            int i = tid + j * 256;
            float v = sm[i];
            if (v > bv) { bv = v; bi = i; }
        }
#pragma unroll
        for (int off = 16; off; off >>= 1) {
            float ov = __shfl_xor_sync(0xffffffffu, bv, off);
            int   oi = __shfl_xor_sync(0xffffffffu, bi, off);
            if (ov > bv || (ov == bv && oi < bi)) { bv = ov; bi = oi; }
        }
        if (lane == 0) { wv[w] = bv; wi[w] = bi; }
        __syncthreads();
        if (w == 0) {
            bv = (lane < 8) ? wv[lane] : -1e30f;
            bi = (lane < 8) ? wi[lane] : (1 << 30);
#pragma unroll
            for (int off = 4; off; off >>= 1) {
                float ov = __shfl_xor_sync(0xffffffffu, bv, off);
                int   oi = __shfl_xor_sync(0xffffffffu, bi, off);
                if (ov > bv || (ov == bv && oi < bi)) { bv = ov; bi = oi; }
            }
            if (lane == 0) { sidx[it] = bi; sm[bi] = -1e30f; }
        }
        __syncthreads();
    }

    for (int i = tid; i < UU; i += 256) g_topidx[bh * UU + i] = sidx[i];
    for (int i = tid; i < UU * DIM; i += 256) {
        int u = i >> 6, d = i & 63;
        float v = q[((size_t)bh * LQ + sidx[u]) * DIM + d];
        g_Qred[(bh * UU + u) * DIM + d] = t32(v) * 0.125f;   // pre-scaled tf32
    }
}

// ---------------- K3: fused flash attention + V colsum ----------------
// grid (BH, NS); block = 45(pad 64) queries x 512 keys (4 tiles of 128).
// rg=w&3: 16-row strip; kh=w>>2: 64-key half of tile.
__global__ __launch_bounds__(256, 2) void k_attn(const float* __restrict__ K,
                                                 const float* __restrict__ V) {
    extern __shared__ float dynsm[];
    float* Qs = dynsm;                 // 64 x 68  (permuted, tf32, pre-scaled)
    float* KP = Qs + 64 * 68;          // 128 x 68 (K tile permuted tf32; reused as P strips)
    float* VT = KP + 128 * 68;         // 64 x 137 (V^T, tf32, odd stride: conflict-free)
    int bh = blockIdx.x, sp = blockIdx.y;
    int tid = threadIdx.x, w = tid >> 5, lane = tid & 31;
    int rg = w & 3, kh = w >> 2, lq = lane >> 2, lr = lane & 3;

    for (int i = tid; i < 64 * 64; i += 256) {
        int r = i >> 6, d = i & 63;
        Qs[r * 68 + PCOL(d)] = (r < UU) ? g_Qred[(bh * UU + r) * DIM + d] : 0.f;
    }

    float O[8][4];
#pragma unroll
    for (int n = 0; n < 8; n++) { O[n][0] = O[n][1] = O[n][2] = O[n][3] = 0.f; }
    float m0 = -1e30f, m1 = -1e30f, l0a = 0.f, l1a = 0.f;
    float vacc = 0.f;                         // V column-sum partial
    const int p0 = PCOL(2 * lr), p1 = PCOL(2 * lr + 1);

    for (int t = 0; t < 4; t++) {
        __syncthreads();                      // prev-tile P/V reads done (covers Qs fill at t=0)
        int s0 = sp * 512 + t * 128;
        const float4* kb = (const float4*)(K + ((size_t)bh * SK + s0) * DIM);
        const float4* vb = (const float4*)(V + ((size_t)bh * SK + s0) * DIM);
        for (int i = tid; i < 128 * 16; i += 256) {
            int r = i >> 4, cb = (i & 15) * 4;
            float4 f = kb[i];
            int base = r * 68 + (cb & ~7) + ((cb & 4) >> 2);
            KP[base]     = t32(f.x);
            KP[base + 2] = t32(f.y);
            KP[base + 4] = t32(f.z);
            KP[base + 6] = t32(f.w);
            float4 g = vb[i];
            VT[(cb + 0) * 137 + r] = t32(g.x);
            VT[(cb + 1) * 137 + r] = t32(g.y);
            VT[(cb + 2) * 137 + r] = t32(g.z);
            VT[(cb + 3) * 137 + r] = t32(g.w);
        }
        __syncthreads();

        // V column sums (thread: col tid&63, 32-row stripe)
        {
            const float* col = VT + (tid & 63) * 137 + (tid >> 6) * 32;
#pragma unroll
            for (int s = 0; s < 32; s++) vacc += col[s];
        }

        // S = Q @ K^T
        float C[8][4];
#pragma unroll
        for (int n = 0; n < 8; n++) { C[n][0] = C[n][1] = C[n][2] = C[n][3] = 0.f; }
#pragma unroll
        for (int ks = 0; ks < 8; ks++) {
            int ra = (16 * rg + lq) * 68 + 8 * ks + 2 * lr;
            uint2 a0 = *(uint2*)&Qs[ra];
            uint2 a1 = *(uint2*)&Qs[ra + 8 * 68];
            unsigned aq[4] = {a0.x, a1.x, a0.y, a1.y};
#pragma unroll
            for (int nt = 0; nt < 8; nt++) {
                uint2 b = *(uint2*)&KP[(64 * kh + 8 * nt + lq) * 68 + 8 * ks + 2 * lr];
                mma8(C[nt], aq, b.x, b.y);
            }
        }

        // online softmax (Q pre-scaled, no scale here)
        float tm0 = -1e30f, tm1 = -1e30f;
#pragma unroll
        for (int nt = 0; nt < 8; nt++) {
            tm0 = fmaxf(tm0, fmaxf(C[nt][0], C[nt][1]));
            tm1 = fmaxf(tm1, fmaxf(C[nt][2], C[nt][3]));
        }
        tm0 = qmaxf(tm0); tm1 = qmaxf(tm1);
        float nm0 = fmaxf(m0, tm0), nm1 = fmaxf(m1, tm1);
        float f0 = __expf(m0 - nm0), f1 = __expf(m1 - nm1);
        float rs0 = 0.f, rs1 = 0.f;
#pragma unroll
        for (int nt = 0; nt < 8; nt++) {
            C[nt][0] = __expf(C[nt][0] - nm0); C[nt][1] = __expf(C[nt][1] - nm0);
            C[nt][2] = __expf(C[nt][2] - nm1); C[nt][3] = __expf(C[nt][3] - nm1);
            rs0 += C[nt][0] + C[nt][1]; rs1 += C[nt][2] + C[nt][3];
            O[nt][0] *= f0; O[nt][1] *= f0; O[nt][2] *= f1; O[nt][3] *= f1;
        }
        rs0 = qsumf(rs0); rs1 = qsumf(rs1);
        l0a = l0a * f0 + rs0; l1a = l1a * f1 + rs1;
        m0 = nm0; m1 = nm1;

        __syncthreads();                      // all warps done reading K tile
        // P -> warp-private smem strip (rows 16w..16w+15), permuted + tf32
        {
            int rb0 = (16 * w + lq) * 68, rb1 = (16 * w + lq + 8) * 68;
#pragma unroll
            for (int nt = 0; nt < 8; nt++) {
                KP[rb0 + 8 * nt + p0] = t32(C[nt][0]);
                KP[rb0 + 8 * nt + p1] = t32(C[nt][1]);
                KP[rb1 + 8 * nt + p0] = t32(C[nt][2]);
                KP[rb1 + 8 * nt + p1] = t32(C[nt][3]);
            }
        }
        __syncwarp();

        // O += P @ V
#pragma unroll
        for (int ks = 0; ks < 8; ks++) {
            int ra = (16 * w + lq) * 68 + 8 * ks + 2 * lr;
            uint2 pa0 = *(uint2*)&KP[ra];
            uint2 pa1 = *(uint2*)&KP[ra + 8 * 68];
            unsigned ap[4] = {pa0.x, pa1.x, pa0.y, pa1.y};
#pragma unroll
            for (int nt = 0; nt < 8; nt++) {
                const float* vp = &VT[(8 * nt + lq) * 137 + 64 * kh + 8 * ks + lr];
                mma8(O[nt], ap, __float_as_uint(vp[0]), __float_as_uint(vp[4]));
            }
        }
    }

    // V colsum exchange (reuse Qs region; all warps past last VT read... sync first)
    __syncthreads();
    Qs[(tid >> 6) * 68 + (tid & 63)] = vacc;
    __syncthreads();
    if (tid < 64) {
        float s = Qs[tid] + Qs[68 + tid] + Qs[2 * 68 + tid] + Qs[3 * 68 + tid];
        g_Vpart[(bh * NS + sp) * DIM + tid] = s;
    }

    // store partials (p = 2*sp + kh)
    int p = sp * 2 + kh;
    int r0 = 16 * rg + lq, r1 = r0 + 8;
    if (r0 < UU) {
        float* dst = &g_actx[((bh * 16 + p) * UU + r0) * DIM];
#pragma unroll
        for (int nt = 0; nt < 8; nt++)
            *(float2*)&dst[8 * nt + 2 * lr] = make_float2(O[nt][0], O[nt][1]);
        if (lr == 0) g_aml[(bh * 16 + p) * UU + r0] = make_float2(m0, l0a);
    }
    if (r1 < UU) {
        float* dst = &g_actx[((bh * 16 + p) * UU + r1) * DIM];
#pragma unroll
        for (int nt = 0; nt < 8; nt++)
            *(float2*)&dst[8 * nt + 2 * lr] = make_float2(O[nt][2], O[nt][3]);
        if (lr == 0) g_aml[(bh * 16 + p) * UU + r1] = make_float2(m1, l1a);
    }
}

// ---------------- K4: broadcast V_sum into entire output ----------------
__global__ void k_fill(float* __restrict__ out) {
    __shared__ float sv[64];
    int bh = blockIdx.x, ry = blockIdx.y, tid = threadIdx.x;
    if (tid < 64) {
        float s = 0.f;
#pragma unroll
        for (int sp = 0; sp < NS; sp++) s += g_Vpart[(bh * NS + sp) * DIM + tid];
        sv[tid] = s;
    }
    __syncthreads();
    float4* o4 = (float4*)(out + ((size_t)bh * LQ + (size_t)ry * 128) * DIM);
    float4 val = ((const float4*)sv)[tid & 15];
    for (int i = tid; i < 128 * 16; i += 256) o4[i] = val;
}

// ---------------- K5: merge 16 partials, normalize, scatter ----------------
__global__ void k_combine(float* __restrict__ out) {
    __shared__ float wgt[UU * 16];
    __shared__ float Lr[UU];
    __shared__ int   idx[UU];
    int bh = blockIdx.x, tid = threadIdx.x;
    if (tid < UU) {
        float2 ml[16]; float mg = -1e30f;
#pragma unroll
        for (int p = 0; p < 16; p++) {
            ml[p] = g_aml[(bh * 16 + p) * UU + tid];
            mg = fmaxf(mg, ml[p].x);
        }
        float L = 0.f;
#pragma unroll
        for (int p = 0; p < 16; p++) {
            float wv = __expf(ml[p].x - mg);
            wgt[tid * 16 + p] = wv;
            L += wv * ml[p].y;
        }
        Lr[tid] = L;
        idx[tid] = g_topidx[bh * UU + tid];
    }
    __syncthreads();
    for (int i = tid; i < UU * DIM; i += 256) {
        int u = i >> 6, d = i & 63;
        float s = 0.f;
#pragma unroll
        for (int p = 0; p < 16; p++)
            s += wgt[u * 16 + p] * g_actx[((bh * 16 + p) * UU + u) * DIM + d];
        out[((size_t)bh * LQ + idx[u]) * DIM + d] = s / Lr[u];
    }
}

// ---------------- launch ----------------
#define M_SMEM    ((64 * 68 * 2 + 48 * 68 * 2) * 4)
#define ATTN_SMEM ((64 * 68 + 128 * 68 + 64 * 137) * 4)

extern "C" void kernel_launch(void* const* d_in, const int* in_sizes, int n_in,
                              void* d_out, int out_size) {
    const float* q    = (const float*)d_in[0];
    const float* keys = (const float*)d_in[1];
    const float* vals = (const float*)d_in[2];
    const int*   sidx = (const int*)d_in[3];
    float* out = (float*)d_out;

    cudaFuncSetAttribute(k_M,    cudaFuncAttributeMaxDynamicSharedMemorySize, M_SMEM);
    cudaFuncSetAttribute(k_attn, cudaFuncAttributeMaxDynamicSharedMemorySize, ATTN_SMEM);

    k_gather<<<BH, 256>>>(keys, sidx);
    k_M<<<dim3(BH, LQ / 64), 256, M_SMEM>>>(q);
    k_topk<<<BH, 256>>>(q);
    k_attn<<<dim3(BH, NS), 256, ATTN_SMEM>>>(keys, vals);
    k_fill<<<dim3(BH, LQ / 128), 256>>>(out);
    k_combine<<<BH, 256>>>(out);
}

// round 4
// speedup vs baseline: 2.4033x; 1.2272x over previous
#include <cuda_runtime.h>
#include <cuda_bf16.h>

#define BH   128
#define LQ   4096
#define SK   4096
#define DIM  64
#define UU   45
#define NS   8

// col permutation pairing (c, c+4) adjacently within each 8-group (k_M path only)
#define PCOL(c) (((c) & ~7) | (((c) & 3) << 1) | (((c) & 4) >> 2))

// ---------------- scratch ----------------
__device__ float    g_M[BH * LQ];
__device__ int      g_topidx[BH * UU];
__device__ unsigned g_KsHi[BH * 48 * DIM];       // permuted, tf32-hi
__device__ unsigned g_KsLo[BH * 48 * DIM];       // permuted, tf32-lo
__device__ unsigned g_Qbf[BH * UU * 32];         // Q_reduce, bf16x2 packed, pre-scaled
__device__ float    g_Vpart[BH * NS * DIM];
__device__ float    g_actx[BH * 16 * UU * DIM];
__device__ float2   g_aml[BH * 16 * UU];

// ---------------- helpers ----------------
__device__ __forceinline__ unsigned f2tf(float f) {
    unsigned u; asm("cvt.rna.tf32.f32 %0, %1;" : "=r"(u) : "f"(f)); return u;
}
__device__ __forceinline__ float t32(float f) { return __uint_as_float(f2tf(f)); }
__device__ __forceinline__ unsigned packbf(float lo, float hi) {
    unsigned u; asm("cvt.rn.bf16x2.f32 %0, %1, %2;" : "=r"(u) : "f"(hi), "f"(lo)); return u;
}
__device__ __forceinline__ unsigned su32(const void* p) {
    unsigned a;
    asm("{ .reg .u64 t; cvta.to.shared.u64 t, %1; cvt.u32.u64 %0, t; }" : "=r"(a) : "l"(p));
    return a;
}
__device__ __forceinline__ void ldm4(unsigned& r0, unsigned& r1, unsigned& r2, unsigned& r3, unsigned a) {
    asm volatile("ldmatrix.sync.aligned.m8n8.x4.shared.b16 {%0,%1,%2,%3}, [%4];"
                 : "=r"(r0), "=r"(r1), "=r"(r2), "=r"(r3) : "r"(a));
}
__device__ __forceinline__ void ldm4t(unsigned& r0, unsigned& r1, unsigned& r2, unsigned& r3, unsigned a) {
    asm volatile("ldmatrix.sync.aligned.m8n8.x4.trans.shared.b16 {%0,%1,%2,%3}, [%4];"
                 : "=r"(r0), "=r"(r1), "=r"(r2), "=r"(r3) : "r"(a));
}
__device__ __forceinline__ void mma8(float* d, const unsigned* a, unsigned b0, unsigned b1) {
    asm volatile("mma.sync.aligned.m16n8k8.row.col.f32.tf32.tf32.f32 "
                 "{%0,%1,%2,%3}, {%4,%5,%6,%7}, {%8,%9}, {%0,%1,%2,%3};"
                 : "+f"(d[0]), "+f"(d[1]), "+f"(d[2]), "+f"(d[3])
                 : "r"(a[0]), "r"(a[1]), "r"(a[2]), "r"(a[3]), "r"(b0), "r"(b1));
}
__device__ __forceinline__ void mma16(float* d, const unsigned* a, unsigned b0, unsigned b1) {
    asm volatile("mma.sync.aligned.m16n8k16.row.col.f32.bf16.bf16.f32 "
                 "{%0,%1,%2,%3}, {%4,%5,%6,%7}, {%8,%9}, {%0,%1,%2,%3};"
                 : "+f"(d[0]), "+f"(d[1]), "+f"(d[2]), "+f"(d[3])
                 : "r"(a[0]), "r"(a[1]), "r"(a[2]), "r"(a[3]), "r"(b0), "r"(b1));
}
__device__ __forceinline__ float qmaxf(float v) {
    v = fmaxf(v, __shfl_xor_sync(0xffffffffu, v, 1));
    v = fmaxf(v, __shfl_xor_sync(0xffffffffu, v, 2));
    return v;
}
__device__ __forceinline__ float qsumf(float v) {
    v += __shfl_xor_sync(0xffffffffu, v, 1);
    v += __shfl_xor_sync(0xffffffffu, v, 2);
    return v;
}

// ---------------- K0: gather sampled keys, split hi/lo, permute ----------------
__global__ void k_gather(const float* __restrict__ keys, const int* __restrict__ sidx) {
    int bh = blockIdx.x;
    for (int i = threadIdx.x; i < 48 * DIM; i += 256) {
        int u = i >> 6, d = i & 63;
        float v = (u < UU) ? keys[((size_t)bh * SK + sidx[u]) * DIM + d] : 0.f;
        unsigned hi = __float_as_uint(v) & 0xffffe000u;
        unsigned lo = f2tf(v - __uint_as_float(hi));
        g_KsHi[bh * 48 * DIM + u * DIM + PCOL(d)] = hi;
        g_KsLo[bh * 48 * DIM + u * DIM + PCOL(d)] = lo;
    }
}

// ---------------- K1: M via 3xTF32 tensor GEMM (fp32-accurate) ----------------
__global__ __launch_bounds__(256) void k_M(const float* __restrict__ q) {
    extern __shared__ float dynsm[];
    unsigned* Qhi = (unsigned*)dynsm;          // 64*68
    unsigned* Qlo = Qhi + 64 * 68;
    unsigned* Khi = Qlo + 64 * 68;             // 48*68
    unsigned* Klo = Khi + 48 * 68;
    __shared__ float redmx[2][64], redsm[2][64];

    int bh = blockIdx.x, l0 = blockIdx.y * 64;
    int tid = threadIdx.x, w = tid >> 5, lane = tid & 31;
    int rg = w & 3, kh = w >> 2, lq = lane >> 2, lr = lane & 3;

    const float4* qb4 = (const float4*)(q + ((size_t)bh * LQ + l0) * DIM);
    for (int i = tid; i < 64 * 16; i += 256) {
        int r = i >> 4, cb = (i & 15) * 4;
        float4 f = qb4[i];
        int base = r * 68 + (cb & ~7) + ((cb & 4) >> 2);
        float vv[4] = {f.x, f.y, f.z, f.w};
#pragma unroll
        for (int j = 0; j < 4; j++) {
            unsigned hi = __float_as_uint(vv[j]) & 0xffffe000u;
            Qhi[base + 2 * j] = hi;
            Qlo[base + 2 * j] = f2tf(vv[j] - __uint_as_float(hi));
        }
    }
    for (int i = tid; i < 48 * 64; i += 256) {
        int r = i >> 6, c = i & 63;
        Khi[r * 68 + c] = g_KsHi[bh * 48 * DIM + i];
        Klo[r * 68 + c] = g_KsLo[bh * 48 * DIM + i];
    }
    __syncthreads();

    float C[3][4];
#pragma unroll
    for (int n = 0; n < 3; n++) { C[n][0] = C[n][1] = C[n][2] = C[n][3] = 0.f; }

#pragma unroll
    for (int ks = 0; ks < 8; ks++) {
        int ra = (16 * rg + lq) * 68 + 8 * ks + 2 * lr;
        uint2 h0 = *(uint2*)&Qhi[ra];
        uint2 h1 = *(uint2*)&Qhi[ra + 8 * 68];
        uint2 q0 = *(uint2*)&Qlo[ra];
        uint2 q1 = *(uint2*)&Qlo[ra + 8 * 68];
        unsigned ah[4] = {h0.x, h1.x, h0.y, h1.y};
        unsigned al[4] = {q0.x, q1.x, q0.y, q1.y};
#pragma unroll
        for (int nt = 0; nt < 3; nt++) {
            int rb = (24 * kh + 8 * nt + lq) * 68 + 8 * ks + 2 * lr;
            uint2 bhv = *(uint2*)&Khi[rb];
            uint2 blv = *(uint2*)&Klo[rb];
            mma8(C[nt], ah, bhv.x, bhv.y);
            mma8(C[nt], ah, blv.x, blv.y);
            mma8(C[nt], al, bhv.x, bhv.y);
        }
    }

    float mx0 = -1e30f, mx1 = -1e30f, sm0 = 0.f, sm1 = 0.f;
#pragma unroll
    for (int nt = 0; nt < 3; nt++) {
        int c0 = 24 * kh + 8 * nt + 2 * lr;
        sm0 += C[nt][0] + C[nt][1];
        sm1 += C[nt][2] + C[nt][3];
        if (c0 < UU)     { mx0 = fmaxf(mx0, C[nt][0]); mx1 = fmaxf(mx1, C[nt][2]); }
        if (c0 + 1 < UU) { mx0 = fmaxf(mx0, C[nt][1]); mx1 = fmaxf(mx1, C[nt][3]); }
    }
    mx0 = qmaxf(mx0); mx1 = qmaxf(mx1); sm0 = qsumf(sm0); sm1 = qsumf(sm1);
    if (lr == 0) {
        int r0 = 16 * rg + lq;
        redmx[kh][r0] = mx0; redmx[kh][r0 + 8] = mx1;
        redsm[kh][r0] = sm0; redsm[kh][r0 + 8] = sm1;
    }
    __syncthreads();
    if (tid < 64)
        g_M[bh * LQ + l0 + tid] = fmaxf(redmx[0][tid], redmx[1][tid]) -
                                  (redsm[0][tid] + redsm[1][tid]) * (1.0f / SK);
}

// ---------------- K2: top-45 + gather/pack Q_reduce to bf16 (pre-scaled) ----------------
__global__ __launch_bounds__(256) void k_topk(const float* __restrict__ q) {
    __shared__ float sm[LQ];
    __shared__ float wv[8];
    __shared__ int   wi[8];
    __shared__ int   sidx[UU];
    int bh = blockIdx.x, tid = threadIdx.x, w = tid >> 5, lane = tid & 31;

    for (int i = tid; i < LQ; i += 256) sm[i] = g_M[bh * LQ + i];
    __syncthreads();

    for (int it = 0; it < UU; it++) {
        float bv = -1e30f; int bi = 1 << 30;
#pragma unroll
        for (int j = 0; j < 16; j++) {
            int i = tid + j * 256;
            float v = sm[i];
            if (v > bv) { bv = v; bi = i; }
        }
#pragma unroll
        for (int off = 16; off; off >>= 1) {
            float ov = __shfl_xor_sync(0xffffffffu, bv, off);
            int   oi = __shfl_xor_sync(0xffffffffu, bi, off);
            if (ov > bv || (ov == bv && oi < bi)) { bv = ov; bi = oi; }
        }
        if (lane == 0) { wv[w] = bv; wi[w] = bi; }
        __syncthreads();
        if (w == 0) {
            bv = (lane < 8) ? wv[lane] : -1e30f;
            bi = (lane < 8) ? wi[lane] : (1 << 30);
#pragma unroll
            for (int off = 4; off; off >>= 1) {
                float ov = __shfl_xor_sync(0xffffffffu, bv, off);
                int   oi = __shfl_xor_sync(0xffffffffu, bi, off);
                if (ov > bv || (ov == bv && oi < bi)) { bv = ov; bi = oi; }
            }
            if (lane == 0) { sidx[it] = bi; sm[bi] = -1e30f; }
        }
        __syncthreads();
    }

    for (int i = tid; i < UU; i += 256) g_topidx[bh * UU + i] = sidx[i];
    for (int i = tid; i < UU * 32; i += 256) {
        int u = i >> 5, c2 = i & 31;
        float2 qv = *(const float2*)&q[((size_t)bh * LQ + sidx[u]) * DIM + 2 * c2];
        g_Qbf[(bh * UU + u) * 32 + c2] = packbf(qv.x * 0.125f, qv.y * 0.125f);
    }
}

// ---------------- K3: fused bf16 flash attention + fp32 V colsum ----------------
// grid (BH, NS); block = 45(pad 64) q x 512 keys (4 tiles of 128).
// rg=w&3: 16-row q strip; kh=w>>2: 64-key half of tile.
// smem (uints): Qs[64*36] | Ks[128*36] | Vs[128*36] | Ps[64*68]
__global__ __launch_bounds__(256, 2) void k_attn(const float* __restrict__ K,
                                                 const float* __restrict__ V) {
    extern __shared__ unsigned dynu[];
    unsigned* Qsu = dynu;                  // 64 x 36 (72 bf16/row)
    unsigned* Ksu = Qsu + 64 * 36;         // 128 x 36
    unsigned* Vsu = Ksu + 128 * 36;        // 128 x 36
    unsigned* Pu  = Vsu + 128 * 36;        // 64 x 68 (136 bf16/row)

    int bh = blockIdx.x, sp = blockIdx.y;
    int tid = threadIdx.x, w = tid >> 5, lane = tid & 31;
    int rg = w & 3, kh = w >> 2, lq = lane >> 2, lr = lane & 3;
    int mi = lane >> 3, mrow = lane & 7;

    // fill Q tile (bf16x2, pre-scaled)
    for (int i = tid; i < 64 * 32; i += 256) {
        int r = i >> 5, c2 = i & 31;
        Qsu[r * 36 + c2] = (r < UU) ? g_Qbf[(bh * UU + r) * 32 + c2] : 0u;
    }
    __syncthreads();

    // hoist Q fragments (16 regs, reused for all tiles)
    unsigned qbase = su32(Qsu);
    unsigned aq[4][4];
#pragma unroll
    for (int ks = 0; ks < 4; ks++) {
        unsigned a = qbase + ((16 * rg + (mi & 1) * 8 + mrow) * 36 + 8 * ks + (mi >> 1) * 4) * 4;
        ldm4(aq[ks][0], aq[ks][1], aq[ks][2], aq[ks][3], a);
    }

    unsigned kbase = su32(Ksu), vbase = su32(Vsu), pbase = su32(Pu);

    float O[8][4];
#pragma unroll
    for (int n = 0; n < 8; n++) { O[n][0] = O[n][1] = O[n][2] = O[n][3] = 0.f; }
    float m0 = -1e30f, m1 = -1e30f, l0a = 0.f, l1a = 0.f;
    float4 vacc = make_float4(0.f, 0.f, 0.f, 0.f);    // fp32 V column sums

    for (int t = 0; t < 4; t++) {
        __syncthreads();                   // prior tile's K/V reads complete
        int s0 = sp * 512 + t * 128;
        const float4* kb = (const float4*)(K + ((size_t)bh * SK + s0) * DIM);
        const float4* vb = (const float4*)(V + ((size_t)bh * SK + s0) * DIM);
#pragma unroll
        for (int it = 0; it < 8; it++) {
            int i = tid + it * 256;
            int r = i >> 4, cb = i & 15;
            float4 f = kb[i];
            *(uint2*)&Ksu[r * 36 + 2 * cb] = make_uint2(packbf(f.x, f.y), packbf(f.z, f.w));
            float4 g = vb[i];
            vacc.x += g.x; vacc.y += g.y; vacc.z += g.z; vacc.w += g.w;
            *(uint2*)&Vsu[r * 36 + 2 * cb] = make_uint2(packbf(g.x, g.y), packbf(g.z, g.w));
        }
        __syncthreads();

        // S = Q @ K^T  (warp: 16 q rows x 64 keys of its half)
        float C[8][4];
#pragma unroll
        for (int n = 0; n < 8; n++) { C[n][0] = C[n][1] = C[n][2] = C[n][3] = 0.f; }
#pragma unroll
        for (int ks = 0; ks < 4; ks++) {
#pragma unroll
            for (int nt2 = 0; nt2 < 4; nt2++) {
                unsigned b0, b1, b2, b3;
                unsigned a = kbase + ((64 * kh + 16 * nt2 + (mi & 1) * 8 + mrow) * 36 +
                                      8 * ks + (mi >> 1) * 4) * 4;
                ldm4(b0, b1, b2, b3, a);
                mma16(C[2 * nt2],     aq[ks], b0, b2);
                mma16(C[2 * nt2 + 1], aq[ks], b1, b3);
            }
        }

        // online softmax (rows lq, lq+8)
        float tm0 = -1e30f, tm1 = -1e30f;
#pragma unroll
        for (int nt = 0; nt < 8; nt++) {
            tm0 = fmaxf(tm0, fmaxf(C[nt][0], C[nt][1]));
            tm1 = fmaxf(tm1, fmaxf(C[nt][2], C[nt][3]));
        }
        tm0 = qmaxf(tm0); tm1 = qmaxf(tm1);
        float nm0 = fmaxf(m0, tm0), nm1 = fmaxf(m1, tm1);
        float f0 = __expf(m0 - nm0), f1 = __expf(m1 - nm1);
        float rs0 = 0.f, rs1 = 0.f;
#pragma unroll
        for (int nt = 0; nt < 8; nt++) {
            C[nt][0] = __expf(C[nt][0] - nm0); C[nt][1] = __expf(C[nt][1] - nm0);
            C[nt][2] = __expf(C[nt][2] - nm1); C[nt][3] = __expf(C[nt][3] - nm1);
            rs0 += C[nt][0] + C[nt][1]; rs1 += C[nt][2] + C[nt][3];
            O[nt][0] *= f0; O[nt][1] *= f0; O[nt][2] *= f1; O[nt][3] *= f1;
        }
        rs0 = qsumf(rs0); rs1 = qsumf(rs1);
        l0a = l0a * f0 + rs0; l1a = l1a * f1 + rs1;
        m0 = nm0; m1 = nm1;

        // P -> smem bf16 (warp-private cells: rows 16rg.., cols 64kh..)
        {
            int rb0 = (16 * rg + lq) * 68 + 32 * kh + lr;
            int rb1 = rb0 + 8 * 68;
#pragma unroll
            for (int nt = 0; nt < 8; nt++) {
                Pu[rb0 + 4 * nt] = packbf(C[nt][0], C[nt][1]);
                Pu[rb1 + 4 * nt] = packbf(C[nt][2], C[nt][3]);
            }
        }
        __syncwarp();

        // O += P @ V  (A: own P strip; B: V^T via ldmatrix.trans)
#pragma unroll
        for (int ks = 0; ks < 4; ks++) {
            unsigned ap[4];
            unsigned a = pbase + ((16 * rg + (mi & 1) * 8 + mrow) * 68 +
                                  32 * kh + 8 * ks + (mi >> 1) * 4) * 4;
            ldm4(ap[0], ap[1], ap[2], ap[3], a);
#pragma unroll
            for (int nd2 = 0; nd2 < 4; nd2++) {
                unsigned b0, b1, b2, b3;
                unsigned vb_a = vbase + ((64 * kh + 16 * ks + (mi & 1) * 8 + mrow) * 36 +
                                         8 * nd2 + (mi >> 1) * 4) * 4;
                ldm4t(b0, b1, b2, b3, vb_a);
                mma16(O[2 * nd2],     ap, b0, b1);
                mma16(O[2 * nd2 + 1], ap, b2, b3);
            }
        }
    }

    // fp32 V colsum exchange (Qs region is free)
    float4* sm4 = (float4*)Qsu;
    __syncthreads();
    sm4[tid] = vacc;
    __syncthreads();
    if (tid < 64) {
        int g = tid >> 2, j = tid & 3;
        float s = 0.f;
#pragma unroll
        for (int tt = 0; tt < 16; tt++) {
            const float* p4 = (const float*)&sm4[g + 16 * tt];
            s += p4[j];
        }
        g_Vpart[(bh * NS + sp) * DIM + tid] = s;
    }

    // store partials (p = 2*sp + kh)
    int p = sp * 2 + kh;
    int r0 = 16 * rg + lq, r1 = r0 + 8;
    if (r0 < UU) {
        float* dst = &g_actx[((bh * 16 + p) * UU + r0) * DIM];
#pragma unroll
        for (int nt = 0; nt < 8; nt++)
            *(float2*)&dst[8 * nt + 2 * lr] = make_float2(O[nt][0], O[nt][1]);
        if (lr == 0) g_aml[(bh * 16 + p) * UU + r0] = make_float2(m0, l0a);
    }
    if (r1 < UU) {
        float* dst = &g_actx[((bh * 16 + p) * UU + r1) * DIM];
#pragma unroll
        for (int nt = 0; nt < 8; nt++)
            *(float2*)&dst[8 * nt + 2 * lr] = make_float2(O[nt][2], O[nt][3]);
        if (lr == 0) g_aml[(bh * 16 + p) * UU + r1] = make_float2(m1, l1a);
    }
}

// ---------------- K4: broadcast V_sum into entire output ----------------
__global__ void k_fill(float* __restrict__ out) {
    __shared__ float sv[64];
    int bh = blockIdx.x, ry = blockIdx.y, tid = threadIdx.x;
    if (tid < 64) {
        float s = 0.f;
#pragma unroll
        for (int sp = 0; sp < NS; sp++) s += g_Vpart[(bh * NS + sp) * DIM + tid];
        sv[tid] = s;
    }
    __syncthreads();
    float4* o4 = (float4*)(out + ((size_t)bh * LQ + (size_t)ry * 128) * DIM);
    float4 val = ((const float4*)sv)[tid & 15];
    for (int i = tid; i < 128 * 16; i += 256) o4[i] = val;
}

// ---------------- K5: merge 16 partials, normalize, scatter ----------------
__global__ void k_combine(float* __restrict__ out) {
    __shared__ float wgt[UU * 16];
    __shared__ float Lr[UU];
    __shared__ int   idx[UU];
    int bh = blockIdx.x, tid = threadIdx.x;
    if (tid < UU) {
        float2 ml[16]; float mg = -1e30f;
#pragma unroll
        for (int p = 0; p < 16; p++) {
            ml[p] = g_aml[(bh * 16 + p) * UU + tid];
            mg = fmaxf(mg, ml[p].x);
        }
        float L = 0.f;
#pragma unroll
        for (int p = 0; p < 16; p++) {
            float wv = __expf(ml[p].x - mg);
            wgt[tid * 16 + p] = wv;
            L += wv * ml[p].y;
        }
        Lr[tid] = L;
        idx[tid] = g_topidx[bh * UU + tid];
    }
    __syncthreads();
    for (int i = tid; i < UU * DIM; i += 256) {
        int u = i >> 6, d = i & 63;
        float s = 0.f;
#pragma unroll
        for (int p = 0; p < 16; p++)
            s += wgt[u * 16 + p] * g_actx[((bh * 16 + p) * UU + u) * DIM + d];
        out[((size_t)bh * LQ + idx[u]) * DIM + d] = s / Lr[u];
    }
}

// ---------------- launch ----------------
#define M_SMEM    ((64 * 68 * 2 + 48 * 68 * 2) * 4)
#define ATTN_SMEM ((64 * 36 + 128 * 36 + 128 * 36 + 64 * 68) * 4)

extern "C" void kernel_launch(void* const* d_in, const int* in_sizes, int n_in,
                              void* d_out, int out_size) {
    const float* q    = (const float*)d_in[0];
    const float* keys = (const float*)d_in[1];
    const float* vals = (const float*)d_in[2];
    const int*   sidx = (const int*)d_in[3];
    float* out = (float*)d_out;

    cudaFuncSetAttribute(k_M,    cudaFuncAttributeMaxDynamicSharedMemorySize, M_SMEM);
    cudaFuncSetAttribute(k_attn, cudaFuncAttributeMaxDynamicSharedMemorySize, ATTN_SMEM);

    k_gather<<<BH, 256>>>(keys, sidx);
    k_M<<<dim3(BH, LQ / 64), 256, M_SMEM>>>(q);
    k_topk<<<BH, 256>>>(q);
    k_attn<<<dim3(BH, NS), 256, ATTN_SMEM>>>(keys, vals);
    k_fill<<<dim3(BH, LQ / 128), 256>>>(out);
    k_combine<<<BH, 256>>>(out);
}

// round 6
// speedup vs baseline: 3.1131x; 1.2954x over previous
#include <cuda_runtime.h>
#include <cuda_bf16.h>

#define BH   128
#define LQ   4096
#define SK   4096
#define DIM  64
#define UU   45
#define NS   8
#define CAP  160          // candidate cap (expected ~52)
#define MARGIN 0.4f       // >> 6-sigma of bf16 M-tilde error

// ---------------- scratch ----------------
__device__ float    g_M[BH * LQ];                // M-tilde (bf16 GEMM)
__device__ int      g_topidx[BH * UU];
__device__ float    g_Ksamp[BH * UU * DIM];      // fp32 sampled keys
__device__ unsigned g_Ksb[BH * 48 * 32];         // bf16x2 packed sampled keys (padded)
__device__ unsigned g_Qbf[BH * UU * 32];         // Q_reduce, bf16x2, pre-scaled
__device__ float    g_Vpart[BH * NS * DIM];
__device__ float    g_actx[BH * 16 * UU * DIM];
__device__ float2   g_aml[BH * 16 * UU];

// ---------------- helpers ----------------
__device__ __forceinline__ unsigned packbf(float lo, float hi) {
    unsigned u; asm("cvt.rn.bf16x2.f32 %0, %1, %2;" : "=r"(u) : "f"(hi), "f"(lo)); return u;
}
__device__ __forceinline__ unsigned su32(const void* p) {
    unsigned a;
    asm("{ .reg .u64 t; cvta.to.shared.u64 t, %1; cvt.u32.u64 %0, t; }" : "=r"(a) : "l"(p));
    return a;
}
__device__ __forceinline__ void ldm4(unsigned& r0, unsigned& r1, unsigned& r2, unsigned& r3, unsigned a) {
    asm volatile("ldmatrix.sync.aligned.m8n8.x4.shared.b16 {%0,%1,%2,%3}, [%4];"
                 : "=r"(r0), "=r"(r1), "=r"(r2), "=r"(r3) : "r"(a));
}
__device__ __forceinline__ void ldm4t(unsigned& r0, unsigned& r1, unsigned& r2, unsigned& r3, unsigned a) {
    asm volatile("ldmatrix.sync.aligned.m8n8.x4.trans.shared.b16 {%0,%1,%2,%3}, [%4];"
                 : "=r"(r0), "=r"(r1), "=r"(r2), "=r"(r3) : "r"(a));
}
__device__ __forceinline__ void mma16(float* d, const unsigned* a, unsigned b0, unsigned b1) {
    asm volatile("mma.sync.aligned.m16n8k16.row.col.f32.bf16.bf16.f32 "
                 "{%0,%1,%2,%3}, {%4,%5,%6,%7}, {%8,%9}, {%0,%1,%2,%3};"
                 : "+f"(d[0]), "+f"(d[1]), "+f"(d[2]), "+f"(d[3])
                 : "r"(a[0]), "r"(a[1]), "r"(a[2]), "r"(a[3]), "r"(b0), "r"(b1));
}
__device__ __forceinline__ float qmaxf(float v) {
    v = fmaxf(v, __shfl_xor_sync(0xffffffffu, v, 1));
    v = fmaxf(v, __shfl_xor_sync(0xffffffffu, v, 2));
    return v;
}
__device__ __forceinline__ float qsumf(float v) {
    v += __shfl_xor_sync(0xffffffffu, v, 1);
    v += __shfl_xor_sync(0xffffffffu, v, 2);
    return v;
}

// ---------------- K0: gather sampled keys (fp32 + packed bf16) ----------------
__global__ void k_gather(const float* __restrict__ keys, const int* __restrict__ sidx) {
    int bh = blockIdx.x;
    for (int i = threadIdx.x; i < 48 * 32; i += 256) {
        int u = i >> 5, c2 = i & 31;
        float2 v = make_float2(0.f, 0.f);
        if (u < UU) {
            v = *(const float2*)&keys[((size_t)bh * SK + sidx[u]) * DIM + 2 * c2];
            *(float2*)&g_Ksamp[(bh * UU + u) * DIM + 2 * c2] = v;
        }
        g_Ksb[bh * 48 * 32 + i] = packbf(v.x, v.y);
    }
}

// ---------------- K1: M-tilde via single bf16 GEMM ----------------
// 128 q-rows/block; warp w owns rows 16w..16w+15, full 48 keys, full K=64.
__global__ __launch_bounds__(256) void k_Mb(const float* __restrict__ q) {
    __shared__ unsigned Qb[128 * 36];
    __shared__ unsigned Ksb[48 * 36];
    int bh = blockIdx.x, l0 = blockIdx.y * 128;
    int tid = threadIdx.x, w = tid >> 5, lane = tid & 31;
    int lq = lane >> 2, lr = lane & 3, mi = lane >> 3, mrow = lane & 7;

    const float4* qb4 = (const float4*)(q + ((size_t)bh * LQ + l0) * DIM);
    for (int i = tid; i < 128 * 16; i += 256) {
        int r = i >> 4, cb = i & 15;
        float4 f = qb4[i];
        *(uint2*)&Qb[r * 36 + 2 * cb] = make_uint2(packbf(f.x, f.y), packbf(f.z, f.w));
    }
    for (int i = tid; i < 48 * 32; i += 256) {
        int r = i >> 5, c2 = i & 31;
        Ksb[r * 36 + c2] = g_Ksb[bh * 48 * 32 + i];
    }
    __syncthreads();

    unsigned qbase = su32(Qb), kbase = su32(Ksb);
    unsigned aq[4][4];
#pragma unroll
    for (int ks = 0; ks < 4; ks++) {
        unsigned a = qbase + ((16 * w + (mi & 1) * 8 + mrow) * 36 + 8 * ks + (mi >> 1) * 4) * 4;
        ldm4(aq[ks][0], aq[ks][1], aq[ks][2], aq[ks][3], a);
    }

    float C[6][4];
#pragma unroll
    for (int n = 0; n < 6; n++) { C[n][0] = C[n][1] = C[n][2] = C[n][3] = 0.f; }
#pragma unroll
    for (int ks = 0; ks < 4; ks++) {
#pragma unroll
        for (int nt2 = 0; nt2 < 3; nt2++) {
            unsigned b0, b1, b2, b3;
            unsigned a = kbase + ((16 * nt2 + (mi & 1) * 8 + mrow) * 36 + 8 * ks + (mi >> 1) * 4) * 4;
            ldm4(b0, b1, b2, b3, a);
            mma16(C[2 * nt2],     aq[ks], b0, b2);
            mma16(C[2 * nt2 + 1], aq[ks], b1, b3);
        }
    }

    float mx0 = -1e30f, mx1 = -1e30f, sm0 = 0.f, sm1 = 0.f;
#pragma unroll
    for (int nt = 0; nt < 6; nt++) {
        int c = 8 * nt + 2 * lr;
        sm0 += C[nt][0] + C[nt][1];        // pad cols exact zero
        sm1 += C[nt][2] + C[nt][3];
        if (c < UU)     { mx0 = fmaxf(mx0, C[nt][0]); mx1 = fmaxf(mx1, C[nt][2]); }
        if (c + 1 < UU) { mx0 = fmaxf(mx0, C[nt][1]); mx1 = fmaxf(mx1, C[nt][3]); }
    }
    mx0 = qmaxf(mx0); mx1 = qmaxf(mx1); sm0 = qsumf(sm0); sm1 = qsumf(sm1);
    if (lr == 0) {
        g_M[bh * LQ + l0 + 16 * w + lq]     = mx0 - sm0 * (1.0f / SK);
        g_M[bh * LQ + l0 + 16 * w + lq + 8] = mx1 - sm1 * (1.0f / SK);
    }
}

// ---------------- K2: candidate select + exact recompute + exact top-45 ----------------
__global__ __launch_bounds__(256) void k_sel(const float* __restrict__ q) {
    extern __shared__ float dsm[];
    float* Ks = dsm;                       // 45*64
    float* D  = Ks + UU * DIM;             // CAP*48
    __shared__ float wv[8];
    __shared__ int   wi[8];
    __shared__ float sv_g;
    __shared__ int   si_g;
    __shared__ int   cnt;
    __shared__ int   candIdx[CAP];
    __shared__ float Mex[CAP];
    __shared__ int   sidx[UU];
    __shared__ float thr_s;

    int bh = blockIdx.x, tid = threadIdx.x, w = tid >> 5, lane = tid & 31;

    // ---- phase 1: register top-45 of M-tilde -> threshold ----
    float v[16];
#pragma unroll
    for (int j = 0; j < 16; j++) v[j] = g_M[bh * LQ + tid + 256 * j];
    if (tid == 0) cnt = 0;

    for (int it = 0; it < UU; it++) {
        float bv = -1e30f; int bi = 1 << 30;
#pragma unroll
        for (int j = 0; j < 16; j++)
            if (v[j] > bv) { bv = v[j]; bi = tid + 256 * j; }
#pragma unroll
        for (int off = 16; off; off >>= 1) {
            float ov = __shfl_xor_sync(0xffffffffu, bv, off);
            int   oi = __shfl_xor_sync(0xffffffffu, bi, off);
            if (ov > bv || (ov == bv && oi < bi)) { bv = ov; bi = oi; }
        }
        if (lane == 0) { wv[w] = bv; wi[w] = bi; }
        __syncthreads();
        if (w == 0) {
            bv = (lane < 8) ? wv[lane] : -1e30f;
            bi = (lane < 8) ? wi[lane] : (1 << 30);
#pragma unroll
            for (int off = 4; off; off >>= 1) {
                float ov = __shfl_xor_sync(0xffffffffu, bv, off);
                int   oi = __shfl_xor_sync(0xffffffffu, bi, off);
                if (ov > bv || (ov == bv && oi < bi)) { bv = ov; bi = oi; }
            }
            if (lane == 0) { sv_g = bv; si_g = bi; }
        }
        __syncthreads();
        int win = si_g;
        if ((win & 255) == tid) v[win >> 8] = -1e30f;
        if (it == UU - 1 && tid == 0) thr_s = sv_g - MARGIN;
    }
    __syncthreads();
    float thr = thr_s;

    // ---- phase 2: compact candidates ----
#pragma unroll
    for (int j = 0; j < 16; j++) {
        int i = tid + 256 * j;
        if (g_M[bh * LQ + i] >= thr) {
            int pos = atomicAdd(&cnt, 1);
            if (pos < CAP) candIdx[pos] = i;
        }
    }
    // load sampled keys fp32
    for (int i = tid; i < UU * DIM; i += 256) Ks[i] = g_Ksamp[bh * UU * DIM + i];
    __syncthreads();
    int ccnt = min(cnt, CAP);

    // ---- phase 3: exact fp32 dots for (candidate, key) pairs ----
    int total = ccnt * UU;
    for (int p = tid; p < total; p += 256) {
        int c = p / UU, k = p - c * UU;
        const float4* qr = (const float4*)(q + ((size_t)bh * LQ + candIdx[c]) * DIM);
        const float4* kr = (const float4*)(Ks + k * DIM);
        float acc = 0.f;
#pragma unroll
        for (int d4 = 0; d4 < 16; d4++) {
            float4 a = qr[d4], b = kr[d4];
            acc += a.x * b.x + a.y * b.y + a.z * b.z + a.w * b.w;
        }
        D[c * 48 + k] = acc;
    }
    __syncthreads();

    // ---- phase 4: exact M per candidate ----
    for (int c = tid; c < ccnt; c += 256) {
        float mx = -1e30f, sm = 0.f;
#pragma unroll 5
        for (int k = 0; k < UU; k++) {
            float x = D[c * 48 + k];
            mx = fmaxf(mx, x); sm += x;
        }
        Mex[c] = mx - sm * (1.0f / SK);
    }
    __syncthreads();

    // ---- phase 5: exact top-45 over candidates (tie: smaller original idx) ----
    float val = (tid < ccnt) ? Mex[tid] : -1e30f;
    int   ix  = (tid < ccnt) ? candIdx[tid] : (1 << 30);
    for (int it = 0; it < UU; it++) {
        float bv = val; int bi = ix;
#pragma unroll
        for (int off = 16; off; off >>= 1) {
            float ov = __shfl_xor_sync(0xffffffffu, bv, off);
            int   oi = __shfl_xor_sync(0xffffffffu, bi, off);
            if (ov > bv || (ov == bv && oi < bi)) { bv = ov; bi = oi; }
        }
        if (lane == 0) { wv[w] = bv; wi[w] = bi; }
        __syncthreads();
        if (w == 0) {
            bv = (lane < 8) ? wv[lane] : -1e30f;
            bi = (lane < 8) ? wi[lane] : (1 << 30);
#pragma unroll
            for (int off = 4; off; off >>= 1) {
                float ov = __shfl_xor_sync(0xffffffffu, bv, off);
                int   oi = __shfl_xor_sync(0xffffffffu, bi, off);
                if (ov > bv || (ov == bv && oi < bi)) { bv = ov; bi = oi; }
            }
            if (lane == 0) { sidx[it] = bi; si_g = bi; }
        }
        __syncthreads();
        if (ix == si_g) val = -1e30f;
    }

    // ---- phase 6: write indices + pack Q_reduce bf16 (pre-scaled) ----
    for (int i = tid; i < UU; i += 256) g_topidx[bh * UU + i] = sidx[i];
    for (int i = tid; i < UU * 32; i += 256) {
        int u = i >> 5, c2 = i & 31;
        float2 qv = *(const float2*)&q[((size_t)bh * LQ + sidx[u]) * DIM + 2 * c2];
        g_Qbf[(bh * UU + u) * 32 + c2] = packbf(qv.x * 0.125f, qv.y * 0.125f);
    }
}

// ---------------- K3: fused bf16 flash attention + fp32 V colsum ----------------
__global__ __launch_bounds__(256, 2) void k_attn(const float* __restrict__ K,
                                                 const float* __restrict__ V) {
    extern __shared__ unsigned dynu[];
    unsigned* Qsu = dynu;                  // 64 x 36
    unsigned* Ksu = Qsu + 64 * 36;         // 128 x 36
    unsigned* Vsu = Ksu + 128 * 36;        // 128 x 36
    unsigned* Pu  = Vsu + 128 * 36;        // 64 x 68

    int bh = blockIdx.x, sp = blockIdx.y;
    int tid = threadIdx.x, w = tid >> 5, lane = tid & 31;
    int rg = w & 3, kh = w >> 2, lq = lane >> 2, lr = lane & 3;
    int mi = lane >> 3, mrow = lane & 7;

    for (int i = tid; i < 64 * 32; i += 256) {
        int r = i >> 5, c2 = i & 31;
        Qsu[r * 36 + c2] = (r < UU) ? g_Qbf[(bh * UU + r) * 32 + c2] : 0u;
    }
    __syncthreads();

    unsigned qbase = su32(Qsu);
    unsigned aq[4][4];
#pragma unroll
    for (int ks = 0; ks < 4; ks++) {
        unsigned a = qbase + ((16 * rg + (mi & 1) * 8 + mrow) * 36 + 8 * ks + (mi >> 1) * 4) * 4;
        ldm4(aq[ks][0], aq[ks][1], aq[ks][2], aq[ks][3], a);
    }

    unsigned kbase = su32(Ksu), vbase = su32(Vsu), pbase = su32(Pu);

    float O[8][4];
#pragma unroll
    for (int n = 0; n < 8; n++) { O[n][0] = O[n][1] = O[n][2] = O[n][3] = 0.f; }
    float m0 = -1e30f, m1 = -1e30f, l0a = 0.f, l1a = 0.f;
    float4 vacc = make_float4(0.f, 0.f, 0.f, 0.f);

    for (int t = 0; t < 4; t++) {
        __syncthreads();
        int s0 = sp * 512 + t * 128;
        const float4* kb = (const float4*)(K + ((size_t)bh * SK + s0) * DIM);
        const float4* vb = (const float4*)(V + ((size_t)bh * SK + s0) * DIM);
#pragma unroll
        for (int it = 0; it < 8; it++) {
            int i = tid + it * 256;
            int r = i >> 4, cb = i & 15;
            float4 f = kb[i];
            *(uint2*)&Ksu[r * 36 + 2 * cb] = make_uint2(packbf(f.x, f.y), packbf(f.z, f.w));
            float4 g = vb[i];
            vacc.x += g.x; vacc.y += g.y; vacc.z += g.z; vacc.w += g.w;
            *(uint2*)&Vsu[r * 36 + 2 * cb] = make_uint2(packbf(g.x, g.y), packbf(g.z, g.w));
        }
        __syncthreads();

        float C[8][4];
#pragma unroll
        for (int n = 0; n < 8; n++) { C[n][0] = C[n][1] = C[n][2] = C[n][3] = 0.f; }
#pragma unroll
        for (int ks = 0; ks < 4; ks++) {
#pragma unroll
            for (int nt2 = 0; nt2 < 4; nt2++) {
                unsigned b0, b1, b2, b3;
                unsigned a = kbase + ((64 * kh + 16 * nt2 + (mi & 1) * 8 + mrow) * 36 +
                                      8 * ks + (mi >> 1) * 4) * 4;
                ldm4(b0, b1, b2, b3, a);
                mma16(C[2 * nt2],     aq[ks], b0, b2);
                mma16(C[2 * nt2 + 1], aq[ks], b1, b3);
            }
        }

        float tm0 = -1e30f, tm1 = -1e30f;
#pragma unroll
        for (int nt = 0; nt < 8; nt++) {
            tm0 = fmaxf(tm0, fmaxf(C[nt][0], C[nt][1]));
            tm1 = fmaxf(tm1, fmaxf(C[nt][2], C[nt][3]));
        }
        tm0 = qmaxf(tm0); tm1 = qmaxf(tm1);
        float nm0 = fmaxf(m0, tm0), nm1 = fmaxf(m1, tm1);
        float f0 = __expf(m0 - nm0), f1 = __expf(m1 - nm1);
        float rs0 = 0.f, rs1 = 0.f;
#pragma unroll
        for (int nt = 0; nt < 8; nt++) {
            C[nt][0] = __expf(C[nt][0] - nm0); C[nt][1] = __expf(C[nt][1] - nm0);
            C[nt][2] = __expf(C[nt][2] - nm1); C[nt][3] = __expf(C[nt][3] - nm1);
            rs0 += C[nt][0] + C[nt][1]; rs1 += C[nt][2] + C[nt][3];
            O[nt][0] *= f0; O[nt][1] *= f0; O[nt][2] *= f1; O[nt][3] *= f1;
        }
        rs0 = qsumf(rs0); rs1 = qsumf(rs1);
        l0a = l0a * f0 + rs0; l1a = l1a * f1 + rs1;
        m0 = nm0; m1 = nm1;

        {
            int rb0 = (16 * rg + lq) * 68 + 32 * kh + lr;
            int rb1 = rb0 + 8 * 68;
#pragma unroll
            for (int nt = 0; nt < 8; nt++) {
                Pu[rb0 + 4 * nt] = packbf(C[nt][0], C[nt][1]);
                Pu[rb1 + 4 * nt] = packbf(C[nt][2], C[nt][3]);
            }
        }
        __syncwarp();

#pragma unroll
        for (int ks = 0; ks < 4; ks++) {
            unsigned ap[4];
            unsigned a = pbase + ((16 * rg + (mi & 1) * 8 + mrow) * 68 +
                                  32 * kh + 8 * ks + (mi >> 1) * 4) * 4;
            ldm4(ap[0], ap[1], ap[2], ap[3], a);
#pragma unroll
            for (int nd2 = 0; nd2 < 4; nd2++) {
                unsigned b0, b1, b2, b3;
                unsigned vb_a = vbase + ((64 * kh + 16 * ks + (mi & 1) * 8 + mrow) * 36 +
                                         8 * nd2 + (mi >> 1) * 4) * 4;
                ldm4t(b0, b1, b2, b3, vb_a);
                mma16(O[2 * nd2],     ap, b0, b1);
                mma16(O[2 * nd2 + 1], ap, b2, b3);
            }
        }
    }

    float4* sm4 = (float4*)Qsu;
    __syncthreads();
    sm4[tid] = vacc;
    __syncthreads();
    if (tid < 64) {
        int g = tid >> 2, j = tid & 3;
        float s = 0.f;
#pragma unroll
        for (int tt = 0; tt < 16; tt++) {
            const float* p4 = (const float*)&sm4[g + 16 * tt];
            s += p4[j];
        }
        g_Vpart[(bh * NS + sp) * DIM + tid] = s;
    }

    int p = sp * 2 + kh;
    int r0 = 16 * rg + lq, r1 = r0 + 8;
    if (r0 < UU) {
        float* dst = &g_actx[((bh * 16 + p) * UU + r0) * DIM];
#pragma unroll
        for (int nt = 0; nt < 8; nt++)
            *(float2*)&dst[8 * nt + 2 * lr] = make_float2(O[nt][0], O[nt][1]);
        if (lr == 0) g_aml[(bh * 16 + p) * UU + r0] = make_float2(m0, l0a);
    }
    if (r1 < UU) {
        float* dst = &g_actx[((bh * 16 + p) * UU + r1) * DIM];
#pragma unroll
        for (int nt = 0; nt < 8; nt++)
            *(float2*)&dst[8 * nt + 2 * lr] = make_float2(O[nt][2], O[nt][3]);
        if (lr == 0) g_aml[(bh * 16 + p) * UU + r1] = make_float2(m1, l1a);
    }
}

// ---------------- K4: broadcast V_sum into entire output ----------------
__global__ void k_fill(float* __restrict__ out) {
    __shared__ float sv[64];
    int bh = blockIdx.x, ry = blockIdx.y, tid = threadIdx.x;
    if (tid < 64) {
        float s = 0.f;
#pragma unroll
        for (int sp = 0; sp < NS; sp++) s += g_Vpart[(bh * NS + sp) * DIM + tid];
        sv[tid] = s;
    }
    __syncthreads();
    float4* o4 = (float4*)(out + ((size_t)bh * LQ + (size_t)ry * 128) * DIM);
    float4 val = ((const float4*)sv)[tid & 15];
    for (int i = tid; i < 128 * 16; i += 256) o4[i] = val;
}

// ---------------- K5: merge 16 partials, normalize, scatter ----------------
__global__ void k_combine(float* __restrict__ out) {
    __shared__ float wgt[UU * 16];
    __shared__ float Lr[UU];
    __shared__ int   idx[UU];
    int bh = blockIdx.x, tid = threadIdx.x;
    if (tid < UU) {
        float2 ml[16]; float mg = -1e30f;
#pragma unroll
        for (int p = 0; p < 16; p++) {
            ml[p] = g_aml[(bh * 16 + p) * UU + tid];
            mg = fmaxf(mg, ml[p].x);
        }
        float L = 0.f;
#pragma unroll
        for (int p = 0; p < 16; p++) {
            float wv = __expf(ml[p].x - mg);
            wgt[tid * 16 + p] = wv;
            L += wv * ml[p].y;
        }
        Lr[tid] = L;
        idx[tid] = g_topidx[bh * UU + tid];
    }
    __syncthreads();
    for (int i = tid; i < UU * DIM; i += 256) {
        int u = i >> 6, d = i & 63;
        float s = 0.f;
#pragma unroll
        for (int p = 0; p < 16; p++)
            s += wgt[u * 16 + p] * g_actx[((bh * 16 + p) * UU + u) * DIM + d];
        out[((size_t)bh * LQ + idx[u]) * DIM + d] = s / Lr[u];
    }
}

// ---------------- launch ----------------
#define ATTN_SMEM ((64 * 36 + 128 * 36 + 128 * 36 + 64 * 68) * 4)
#define SEL_SMEM  ((UU * DIM + CAP * 48) * 4)

extern "C" void kernel_launch(void* const* d_in, const int* in_sizes, int n_in,
                              void* d_out, int out_size) {
    const float* q    = (const float*)d_in[0];
    const float* keys = (const float*)d_in[1];
    const float* vals = (const float*)d_in[2];
    const int*   sidx = (const int*)d_in[3];
    float* out = (float*)d_out;

    cudaFuncSetAttribute(k_attn, cudaFuncAttributeMaxDynamicSharedMemorySize, ATTN_SMEM);
    cudaFuncSetAttribute(k_sel,  cudaFuncAttributeMaxDynamicSharedMemorySize, SEL_SMEM);

    k_gather<<<BH, 256>>>(keys, sidx);
    k_Mb<<<dim3(BH, LQ / 128), 256>>>(q);
    k_sel<<<BH, 256, SEL_SMEM>>>(q);
    k_attn<<<dim3(BH, NS), 256, ATTN_SMEM>>>(keys, vals);
    k_fill<<<dim3(BH, LQ / 128), 256>>>(out);
    k_combine<<<BH, 256>>>(out);
}

// round 7
// speedup vs baseline: 3.6030x; 1.1574x over previous
#include <cuda_runtime.h>
#include <cuda_bf16.h>

#define BH   128
#define LQ   4096
#define SK   4096
#define DIM  64
#define UU   45
#define NS   8
#define CAP  160
#define MARGIN 0.4f

// ---------------- scratch ----------------
__device__ float    g_M[BH * LQ];
__device__ int      g_topidx[BH * UU];
__device__ float    g_Ksamp[BH * UU * DIM];
__device__ unsigned g_Ksb[BH * 48 * 32];
__device__ unsigned g_Qbf[BH * UU * 32];
__device__ float    g_Vpart[BH * NS * DIM];
__device__ float    g_actx[BH * 16 * UU * DIM];
__device__ float2   g_aml[BH * 16 * UU];

// ---------------- helpers ----------------
__device__ __forceinline__ unsigned packbf(float lo, float hi) {
    unsigned u; asm("cvt.rn.bf16x2.f32 %0, %1, %2;" : "=r"(u) : "f"(hi), "f"(lo)); return u;
}
__device__ __forceinline__ unsigned su32(const void* p) {
    unsigned a;
    asm("{ .reg .u64 t; cvta.to.shared.u64 t, %1; cvt.u32.u64 %0, t; }" : "=r"(a) : "l"(p));
    return a;
}
__device__ __forceinline__ void ldm4(unsigned& r0, unsigned& r1, unsigned& r2, unsigned& r3, unsigned a) {
    asm volatile("ldmatrix.sync.aligned.m8n8.x4.shared.b16 {%0,%1,%2,%3}, [%4];"
                 : "=r"(r0), "=r"(r1), "=r"(r2), "=r"(r3) : "r"(a));
}
__device__ __forceinline__ void ldm4t(unsigned& r0, unsigned& r1, unsigned& r2, unsigned& r3, unsigned a) {
    asm volatile("ldmatrix.sync.aligned.m8n8.x4.trans.shared.b16 {%0,%1,%2,%3}, [%4];"
                 : "=r"(r0), "=r"(r1), "=r"(r2), "=r"(r3) : "r"(a));
}
__device__ __forceinline__ void mma16(float* d, const unsigned* a, unsigned b0, unsigned b1) {
    asm volatile("mma.sync.aligned.m16n8k16.row.col.f32.bf16.bf16.f32 "
                 "{%0,%1,%2,%3}, {%4,%5,%6,%7}, {%8,%9}, {%0,%1,%2,%3};"
                 : "+f"(d[0]), "+f"(d[1]), "+f"(d[2]), "+f"(d[3])
                 : "r"(a[0]), "r"(a[1]), "r"(a[2]), "r"(a[3]), "r"(b0), "r"(b1));
}
__device__ __forceinline__ float qmaxf(float v) {
    v = fmaxf(v, __shfl_xor_sync(0xffffffffu, v, 1));
    v = fmaxf(v, __shfl_xor_sync(0xffffffffu, v, 2));
    return v;
}
__device__ __forceinline__ float qsumf(float v) {
    v += __shfl_xor_sync(0xffffffffu, v, 1);
    v += __shfl_xor_sync(0xffffffffu, v, 2);
    return v;
}
#define CP16(dst, src) asm volatile("cp.async.cg.shared.global [%0], [%1], 16;" :: "r"(dst), "l"(src))
#define CPCOMMIT()     asm volatile("cp.async.commit_group;" ::: "memory")
#define CPWAIT0()      asm volatile("cp.async.wait_group 0;" ::: "memory")

// ---------------- K0: gather sampled keys (fp32 + packed bf16) ----------------
__global__ void k_gather(const float* __restrict__ keys, const int* __restrict__ sidx) {
    int bh = blockIdx.x;
    for (int i = threadIdx.x; i < 48 * 32; i += 256) {
        int u = i >> 5, c2 = i & 31;
        float2 v = make_float2(0.f, 0.f);
        if (u < UU) {
            v = *(const float2*)&keys[((size_t)bh * SK + sidx[u]) * DIM + 2 * c2];
            *(float2*)&g_Ksamp[(bh * UU + u) * DIM + 2 * c2] = v;
        }
        g_Ksb[bh * 48 * 32 + i] = packbf(v.x, v.y);
    }
}

// ---------------- K1: M-tilde via single bf16 GEMM ----------------
__global__ __launch_bounds__(256) void k_Mb(const float* __restrict__ q) {
    __shared__ unsigned Qb[128 * 36];
    __shared__ unsigned Ksb[48 * 36];
    int bh = blockIdx.x, l0 = blockIdx.y * 128;
    int tid = threadIdx.x, w = tid >> 5, lane = tid & 31;
    int lq = lane >> 2, lr = lane & 3, mi = lane >> 3, mrow = lane & 7;

    const float4* qb4 = (const float4*)(q + ((size_t)bh * LQ + l0) * DIM);
    for (int i = tid; i < 128 * 16; i += 256) {
        int r = i >> 4, cb = i & 15;
        float4 f = qb4[i];
        *(uint2*)&Qb[r * 36 + 2 * cb] = make_uint2(packbf(f.x, f.y), packbf(f.z, f.w));
    }
    for (int i = tid; i < 48 * 32; i += 256) {
        int r = i >> 5, c2 = i & 31;
        Ksb[r * 36 + c2] = g_Ksb[bh * 48 * 32 + i];
    }
    __syncthreads();

    unsigned qbase = su32(Qb), kbase = su32(Ksb);
    unsigned aq[4][4];
#pragma unroll
    for (int ks = 0; ks < 4; ks++) {
        unsigned a = qbase + ((16 * w + (mi & 1) * 8 + mrow) * 36 + 8 * ks + (mi >> 1) * 4) * 4;
        ldm4(aq[ks][0], aq[ks][1], aq[ks][2], aq[ks][3], a);
    }

    float C[6][4];
#pragma unroll
    for (int n = 0; n < 6; n++) { C[n][0] = C[n][1] = C[n][2] = C[n][3] = 0.f; }
#pragma unroll
    for (int ks = 0; ks < 4; ks++) {
#pragma unroll
        for (int nt2 = 0; nt2 < 3; nt2++) {
            unsigned b0, b1, b2, b3;
            unsigned a = kbase + ((16 * nt2 + (mi & 1) * 8 + mrow) * 36 + 8 * ks + (mi >> 1) * 4) * 4;
            ldm4(b0, b1, b2, b3, a);
            mma16(C[2 * nt2],     aq[ks], b0, b2);
            mma16(C[2 * nt2 + 1], aq[ks], b1, b3);
        }
    }

    float mx0 = -1e30f, mx1 = -1e30f, sm0 = 0.f, sm1 = 0.f;
#pragma unroll
    for (int nt = 0; nt < 6; nt++) {
        int c = 8 * nt + 2 * lr;
        sm0 += C[nt][0] + C[nt][1];
        sm1 += C[nt][2] + C[nt][3];
        if (c < UU)     { mx0 = fmaxf(mx0, C[nt][0]); mx1 = fmaxf(mx1, C[nt][2]); }
        if (c + 1 < UU) { mx0 = fmaxf(mx0, C[nt][1]); mx1 = fmaxf(mx1, C[nt][3]); }
    }
    mx0 = qmaxf(mx0); mx1 = qmaxf(mx1); sm0 = qsumf(sm0); sm1 = qsumf(sm1);
    if (lr == 0) {
        g_M[bh * LQ + l0 + 16 * w + lq]     = mx0 - sm0 * (1.0f / SK);
        g_M[bh * LQ + l0 + 16 * w + lq + 8] = mx1 - sm1 * (1.0f / SK);
    }
}

// ---------------- K2: bisection threshold + exact recompute + bitonic top-45 ----------------
__global__ __launch_bounds__(256) void k_sel(const float* __restrict__ q) {
    extern __shared__ float dsm[];
    float* Ks = dsm;                       // 45*64
    float* D  = Ks + UU * DIM;             // CAP*48
    __shared__ float redA[8], redB[8];
    __shared__ int   icnt[8];
    __shared__ unsigned long long skey[256];
    __shared__ int   candIdx[CAP];
    __shared__ float Mex[CAP];
    __shared__ int   sidx[UU];
    __shared__ int   cnt;
    __shared__ float bc[2];

    int bh = blockIdx.x, tid = threadIdx.x, w = tid >> 5, lane = tid & 31;

    float v[16];
#pragma unroll
    for (int j = 0; j < 16; j++) v[j] = g_M[bh * LQ + tid + 256 * j];
    if (tid == 0) cnt = 0;

    // ---- min/max of M-tilde ----
    float mn = v[0], mx = v[0];
#pragma unroll
    for (int j = 1; j < 16; j++) { mn = fminf(mn, v[j]); mx = fmaxf(mx, v[j]); }
#pragma unroll
    for (int off = 16; off; off >>= 1) {
        mn = fminf(mn, __shfl_xor_sync(0xffffffffu, mn, off));
        mx = fmaxf(mx, __shfl_xor_sync(0xffffffffu, mx, off));
    }
    if (lane == 0) { redA[w] = mn; redB[w] = mx; }
    __syncthreads();
    if (tid == 0) {
        float a = redA[0], b = redB[0];
#pragma unroll
        for (int i = 1; i < 8; i++) { a = fminf(a, redA[i]); b = fmaxf(b, redB[i]); }
        bc[0] = a; bc[1] = b;
    }
    __syncthreads();

    // ---- bisection: invariant count(>=lo) >= UU > count(>=hi) ----
    float lo = bc[0], hi = bc[1] + 1.0f;
    for (int it = 0; it < 22; it++) {
        float mid = 0.5f * (lo + hi);
        int c = 0;
#pragma unroll
        for (int j = 0; j < 16; j++) c += (v[j] >= mid) ? 1 : 0;
#pragma unroll
        for (int off = 16; off; off >>= 1) c += __shfl_xor_sync(0xffffffffu, c, off);
        if (lane == 0) icnt[w] = c;
        __syncthreads();
        int tot = icnt[0] + icnt[1] + icnt[2] + icnt[3] +
                  icnt[4] + icnt[5] + icnt[6] + icnt[7];
        if (tot >= UU) lo = mid; else hi = mid;
        __syncthreads();
    }
    float thr = lo - MARGIN;

    // ---- compact candidates ----
#pragma unroll
    for (int j = 0; j < 16; j++) {
        if (v[j] >= thr) {
            int pos = atomicAdd(&cnt, 1);
            if (pos < CAP) candIdx[pos] = tid + 256 * j;
        }
    }
    for (int i = tid; i < UU * DIM; i += 256) Ks[i] = g_Ksamp[bh * UU * DIM + i];
    __syncthreads();
    int ccnt = min(cnt, CAP);

    // ---- exact fp32 dots ----
    int total = ccnt * UU;
    for (int p = tid; p < total; p += 256) {
        int c = p / UU, k = p - c * UU;
        const float4* qr = (const float4*)(q + ((size_t)bh * LQ + candIdx[c]) * DIM);
        const float4* kr = (const float4*)(Ks + k * DIM);
        float acc = 0.f;
#pragma unroll
        for (int d4 = 0; d4 < 16; d4++) {
            float4 a = qr[d4], b = kr[d4];
            acc += a.x * b.x + a.y * b.y + a.z * b.z + a.w * b.w;
        }
        D[c * 48 + k] = acc;
    }
    __syncthreads();

    // ---- exact M per candidate ----
    for (int c = tid; c < ccnt; c += 256) {
        float mxv = -1e30f, smv = 0.f;
#pragma unroll 5
        for (int k = 0; k < UU; k++) {
            float x = D[c * 48 + k];
            mxv = fmaxf(mxv, x); smv += x;
        }
        Mex[c] = mxv - smv * (1.0f / SK);
    }
    __syncthreads();

    // ---- bitonic sort 256 keys: value desc, index asc ----
    unsigned long long key = ~0ull;
    if (tid < ccnt) {
        unsigned u = __float_as_uint(Mex[tid]);
        u = (u & 0x80000000u) ? ~u : (u | 0x80000000u);   // ascending order map
        key = ((unsigned long long)(~u) << 32) | (unsigned)candIdx[tid];
    }
    skey[tid] = key;
    __syncthreads();
#pragma unroll
    for (int k = 2; k <= 256; k <<= 1) {
#pragma unroll
        for (int j = k >> 1; j > 0; j >>= 1) {
            int p = tid ^ j;
            if (p > tid) {
                unsigned long long a = skey[tid], b = skey[p];
                bool up = ((tid & k) == 0);
                if (up ? (a > b) : (a < b)) { skey[tid] = b; skey[p] = a; }
            }
            __syncthreads();
        }
    }
    if (tid < UU) sidx[tid] = (int)(unsigned)(skey[tid] & 0xffffffffu);
    __syncthreads();

    // ---- write indices + pack Q_reduce bf16 (pre-scaled) ----
    for (int i = tid; i < UU; i += 256) g_topidx[bh * UU + i] = sidx[i];
    for (int i = tid; i < UU * 32; i += 256) {
        int u = i >> 5, c2 = i & 31;
        float2 qv = *(const float2*)&q[((size_t)bh * LQ + sidx[u]) * DIM + 2 * c2];
        g_Qbf[(bh * UU + u) * 32 + c2] = packbf(qv.x * 0.125f, qv.y * 0.125f);
    }
}

// ---------------- K3: fused bf16 flash attention, cp.async V pipeline ----------------
// smem: [P (alias Q) 64*68 | Ksu 128*36 | Vsu 128*36 | Vstage 8192 f32]
__global__ __launch_bounds__(256, 2) void k_attn(const float* __restrict__ K,
                                                 const float* __restrict__ V) {
    extern __shared__ unsigned dynu[];
    unsigned* Pu  = dynu;                   // 64*68 (Q lives here during prologue)
    unsigned* Qsu = dynu;
    unsigned* Ksu = dynu + 64 * 68;         // 128*36
    unsigned* Vsu = Ksu + 128 * 36;         // 128*36
    float*    Vst = (float*)(Vsu + 128 * 36); // 128*64 f32 stage

    int bh = blockIdx.x, sp = blockIdx.y;
    int tid = threadIdx.x, w = tid >> 5, lane = tid & 31;
    int rg = w & 3, kh = w >> 2, lq = lane >> 2, lr = lane & 3;
    int mi = lane >> 3, mrow = lane & 7;

    unsigned vst_s = su32(Vst);
    const float* vg = V + ((size_t)bh * SK + (size_t)sp * 512) * DIM;

    // prologue: start async copy of V tile 0
#pragma unroll
    for (int c = 0; c < 8; c++)
        CP16(vst_s + (unsigned)(tid + 256 * c) * 16u, vg + (size_t)(tid + 256 * c) * 4);
    CPCOMMIT();

    // fill Q tile
    for (int i = tid; i < 64 * 32; i += 256) {
        int r = i >> 5, c2 = i & 31;
        Qsu[r * 36 + c2] = (r < UU) ? g_Qbf[(bh * UU + r) * 32 + c2] : 0u;
    }
    __syncthreads();

    unsigned qbase = su32(Qsu);
    unsigned aq[4][4];
#pragma unroll
    for (int ks = 0; ks < 4; ks++) {
        unsigned a = qbase + ((16 * rg + (mi & 1) * 8 + mrow) * 36 + 8 * ks + (mi >> 1) * 4) * 4;
        ldm4(aq[ks][0], aq[ks][1], aq[ks][2], aq[ks][3], a);
    }

    unsigned kbase = su32(Ksu), vbase = su32(Vsu), pbase = su32(Pu);

    float O[8][4];
#pragma unroll
    for (int n = 0; n < 8; n++) { O[n][0] = O[n][1] = O[n][2] = O[n][3] = 0.f; }
    float m0 = -1e30f, m1 = -1e30f, l0a = 0.f, l1a = 0.f;
    float4 vacc = make_float4(0.f, 0.f, 0.f, 0.f);

    for (int t = 0; t < 4; t++) {
        // early K loads (latency overlaps cp.async wait)
        const float4* kb = (const float4*)(K + ((size_t)bh * SK + (size_t)sp * 512 + t * 128) * DIM);
        float4 kr[8];
#pragma unroll
        for (int it = 0; it < 8; it++) kr[it] = kb[tid + it * 256];

        CPWAIT0();
        __syncthreads();                   // V stage ready; prior compute done

        // convert V stage -> bf16 + fp32 colsum (same word mapping as cp.async)
        {
            const float4* st4 = (const float4*)Vst;
#pragma unroll
            for (int c = 0; c < 8; c++) {
                int i = tid + 256 * c;
                float4 g = st4[i];
                vacc.x += g.x; vacc.y += g.y; vacc.z += g.z; vacc.w += g.w;
                int r = i >> 4, cb = i & 15;
                *(uint2*)&Vsu[r * 36 + 2 * cb] = make_uint2(packbf(g.x, g.y), packbf(g.z, g.w));
            }
        }
        // prefetch next V tile into stage (safe: each thread overwrites only words it read)
        if (t < 3) {
            const float* src = vg + (size_t)(t + 1) * 128 * DIM;
#pragma unroll
            for (int c = 0; c < 8; c++)
                CP16(vst_s + (unsigned)(tid + 256 * c) * 16u, src + (size_t)(tid + 256 * c) * 4);
            CPCOMMIT();
        }
        // convert K regs -> bf16
#pragma unroll
        for (int it = 0; it < 8; it++) {
            int i = tid + it * 256;
            int r = i >> 4, cb = i & 15;
            float4 f = kr[it];
            *(uint2*)&Ksu[r * 36 + 2 * cb] = make_uint2(packbf(f.x, f.y), packbf(f.z, f.w));
        }
        __syncthreads();

        // S = Q @ K^T
        float C[8][4];
#pragma unroll
        for (int n = 0; n < 8; n++) { C[n][0] = C[n][1] = C[n][2] = C[n][3] = 0.f; }
#pragma unroll
        for (int ks = 0; ks < 4; ks++) {
#pragma unroll
            for (int nt2 = 0; nt2 < 4; nt2++) {
                unsigned b0, b1, b2, b3;
                unsigned a = kbase + ((64 * kh + 16 * nt2 + (mi & 1) * 8 + mrow) * 36 +
                                      8 * ks + (mi >> 1) * 4) * 4;
                ldm4(b0, b1, b2, b3, a);
                mma16(C[2 * nt2],     aq[ks], b0, b2);
                mma16(C[2 * nt2 + 1], aq[ks], b1, b3);
            }
        }

        // online softmax
        float tm0 = -1e30f, tm1 = -1e30f;
#pragma unroll
        for (int nt = 0; nt < 8; nt++) {
            tm0 = fmaxf(tm0, fmaxf(C[nt][0], C[nt][1]));
            tm1 = fmaxf(tm1, fmaxf(C[nt][2], C[nt][3]));
        }
        tm0 = qmaxf(tm0); tm1 = qmaxf(tm1);
        float nm0 = fmaxf(m0, tm0), nm1 = fmaxf(m1, tm1);
        float f0 = __expf(m0 - nm0), f1 = __expf(m1 - nm1);
        float rs0 = 0.f, rs1 = 0.f;
#pragma unroll
        for (int nt = 0; nt < 8; nt++) {
            C[nt][0] = __expf(C[nt][0] - nm0); C[nt][1] = __expf(C[nt][1] - nm0);
            C[nt][2] = __expf(C[nt][2] - nm1); C[nt][3] = __expf(C[nt][3] - nm1);
            rs0 += C[nt][0] + C[nt][1]; rs1 += C[nt][2] + C[nt][3];
            O[nt][0] *= f0; O[nt][1] *= f0; O[nt][2] *= f1; O[nt][3] *= f1;
        }
        rs0 = qsumf(rs0); rs1 = qsumf(rs1);
        l0a = l0a * f0 + rs0; l1a = l1a * f1 + rs1;
        m0 = nm0; m1 = nm1;

        // P -> smem bf16 (warp-private cells)
        {
            int rb0 = (16 * rg + lq) * 68 + 32 * kh + lr;
            int rb1 = rb0 + 8 * 68;
#pragma unroll
            for (int nt = 0; nt < 8; nt++) {
                Pu[rb0 + 4 * nt] = packbf(C[nt][0], C[nt][1]);
                Pu[rb1 + 4 * nt] = packbf(C[nt][2], C[nt][3]);
            }
        }
        __syncwarp();

        // O += P @ V
#pragma unroll
        for (int ks = 0; ks < 4; ks++) {
            unsigned ap[4];
            unsigned a = pbase + ((16 * rg + (mi & 1) * 8 + mrow) * 68 +
                                  32 * kh + 8 * ks + (mi >> 1) * 4) * 4;
            ldm4(ap[0], ap[1], ap[2], ap[3], a);
#pragma unroll
            for (int nd2 = 0; nd2 < 4; nd2++) {
                unsigned b0, b1, b2, b3;
                unsigned vb_a = vbase + ((64 * kh + 16 * ks + (mi & 1) * 8 + mrow) * 36 +
                                         8 * nd2 + (mi >> 1) * 4) * 4;
                ldm4t(b0, b1, b2, b3, vb_a);
                mma16(O[2 * nd2],     ap, b0, b1);
                mma16(O[2 * nd2 + 1], ap, b2, b3);
            }
        }
    }

    // fp32 V colsum exchange (reuse P region; compute done)
    float4* sm4 = (float4*)dynu;
    __syncthreads();
    sm4[tid] = vacc;
    __syncthreads();
    if (tid < 64) {
        int g = tid >> 2, j = tid & 3;
        float s = 0.f;
#pragma unroll
        for (int tt = 0; tt < 16; tt++) {
            const float* p4 = (const float*)&sm4[g + 16 * tt];
            s += p4[j];
        }
        g_Vpart[(bh * NS + sp) * DIM + tid] = s;
    }

    // store partials (p = 2*sp + kh)
    int p = sp * 2 + kh;
    int r0 = 16 * rg + lq, r1 = r0 + 8;
    if (r0 < UU) {
        float* dst = &g_actx[((bh * 16 + p) * UU + r0) * DIM];
#pragma unroll
        for (int nt = 0; nt < 8; nt++)
            *(float2*)&dst[8 * nt + 2 * lr] = make_float2(O[nt][0], O[nt][1]);
        if (lr == 0) g_aml[(bh * 16 + p) * UU + r0] = make_float2(m0, l0a);
    }
    if (r1 < UU) {
        float* dst = &g_actx[((bh * 16 + p) * UU + r1) * DIM];
#pragma unroll
        for (int nt = 0; nt < 8; nt++)
            *(float2*)&dst[8 * nt + 2 * lr] = make_float2(O[nt][2], O[nt][3]);
        if (lr == 0) g_aml[(bh * 16 + p) * UU + r1] = make_float2(m1, l1a);
    }
}

// ---------------- K4: broadcast V_sum into entire output ----------------
__global__ void k_fill(float* __restrict__ out) {
    __shared__ float sv[64];
    int bh = blockIdx.x, ry = blockIdx.y, tid = threadIdx.x;
    if (tid < 64) {
        float s = 0.f;
#pragma unroll
        for (int sp = 0; sp < NS; sp++) s += g_Vpart[(bh * NS + sp) * DIM + tid];
        sv[tid] = s;
    }
    __syncthreads();
    float4* o4 = (float4*)(out + ((size_t)bh * LQ + (size_t)ry * 128) * DIM);
    float4 val = ((const float4*)sv)[tid & 15];
    for (int i = tid; i < 128 * 16; i += 256) o4[i] = val;
}

// ---------------- K5: merge 16 partials, normalize, scatter ----------------
__global__ void k_combine(float* __restrict__ out) {
    __shared__ float wgt[UU * 16];
    __shared__ float Lr[UU];
    __shared__ int   idx[UU];
    int bh = blockIdx.x, tid = threadIdx.x;
    if (tid < UU) {
        float2 ml[16]; float mg = -1e30f;
#pragma unroll
        for (int p = 0; p < 16; p++) {
            ml[p] = g_aml[(bh * 16 + p) * UU + tid];
            mg = fmaxf(mg, ml[p].x);
        }
        float L = 0.f;
#pragma unroll
        for (int p = 0; p < 16; p++) {
            float wv = __expf(ml[p].x - mg);
            wgt[tid * 16 + p] = wv;
            L += wv * ml[p].y;
        }
        Lr[tid] = L;
        idx[tid] = g_topidx[bh * UU + tid];
    }
    __syncthreads();
    for (int i = tid; i < UU * DIM; i += 256) {
        int u = i >> 6, d = i & 63;
        float s = 0.f;
#pragma unroll
        for (int p = 0; p < 16; p++)
            s += wgt[u * 16 + p] * g_actx[((bh * 16 + p) * UU + u) * DIM + d];
        out[((size_t)bh * LQ + idx[u]) * DIM + d] = s / Lr[u];
    }
}

// ---------------- launch ----------------
#define ATTN_SMEM ((64 * 68 + 128 * 36 + 128 * 36 + 8192) * 4)
#define SEL_SMEM  ((UU * DIM + CAP * 48) * 4)

extern "C" void kernel_launch(void* const* d_in, const int* in_sizes, int n_in,
                              void* d_out, int out_size) {
    const float* q    = (const float*)d_in[0];
    const float* keys = (const float*)d_in[1];
    const float* vals = (const float*)d_in[2];
    const int*   sidx = (const int*)d_in[3];
    float* out = (float*)d_out;

    cudaFuncSetAttribute(k_attn, cudaFuncAttributeMaxDynamicSharedMemorySize, ATTN_SMEM);
    cudaFuncSetAttribute(k_sel,  cudaFuncAttributeMaxDynamicSharedMemorySize, SEL_SMEM);

    k_gather<<<BH, 256>>>(keys, sidx);
    k_Mb<<<dim3(BH, LQ / 128), 256>>>(q);
    k_sel<<<BH, 256, SEL_SMEM>>>(q);
    k_attn<<<dim3(BH, NS), 256, ATTN_SMEM>>>(keys, vals);
    k_fill<<<dim3(BH, LQ / 128), 256>>>(out);
    k_combine<<<BH, 256>>>(out);
}

// round 8
// speedup vs baseline: 3.6094x; 1.0018x over previous
#include <cuda_runtime.h>
#include <cuda_bf16.h>

#define BH   128
#define LQ   4096
#define SK   4096
#define DIM  64
#define UU   45
#define NS   8
#define CAP  160
#define MARGIN 0.4f

// ---------------- scratch ----------------
__device__ float    g_M[BH * LQ];
__device__ int      g_topidx[BH * UU];
__device__ float    g_Ksamp[BH * UU * DIM];
__device__ unsigned g_Ksb[BH * 48 * 32];
__device__ unsigned g_Qbf[BH * UU * 32];
__device__ float    g_Vpart[BH * NS * DIM];
__device__ float    g_actx[BH * 16 * UU * DIM];
__device__ float2   g_aml[BH * 16 * UU];

// ---------------- helpers ----------------
__device__ __forceinline__ unsigned packbf(float lo, float hi) {
    unsigned u; asm("cvt.rn.bf16x2.f32 %0, %1, %2;" : "=r"(u) : "f"(hi), "f"(lo)); return u;
}
__device__ __forceinline__ unsigned su32(const void* p) {
    unsigned a;
    asm("{ .reg .u64 t; cvta.to.shared.u64 t, %1; cvt.u32.u64 %0, t; }" : "=r"(a) : "l"(p));
    return a;
}
__device__ __forceinline__ void ldm4(unsigned& r0, unsigned& r1, unsigned& r2, unsigned& r3, unsigned a) {
    asm volatile("ldmatrix.sync.aligned.m8n8.x4.shared.b16 {%0,%1,%2,%3}, [%4];"
                 : "=r"(r0), "=r"(r1), "=r"(r2), "=r"(r3) : "r"(a));
}
__device__ __forceinline__ void ldm4t(unsigned& r0, unsigned& r1, unsigned& r2, unsigned& r3, unsigned a) {
    asm volatile("ldmatrix.sync.aligned.m8n8.x4.trans.shared.b16 {%0,%1,%2,%3}, [%4];"
                 : "=r"(r0), "=r"(r1), "=r"(r2), "=r"(r3) : "r"(a));
}
__device__ __forceinline__ void mma16(float* d, const unsigned* a, unsigned b0, unsigned b1) {
    asm volatile("mma.sync.aligned.m16n8k16.row.col.f32.bf16.bf16.f32 "
                 "{%0,%1,%2,%3}, {%4,%5,%6,%7}, {%8,%9}, {%0,%1,%2,%3};"
                 : "+f"(d[0]), "+f"(d[1]), "+f"(d[2]), "+f"(d[3])
                 : "r"(a[0]), "r"(a[1]), "r"(a[2]), "r"(a[3]), "r"(b0), "r"(b1));
}
__device__ __forceinline__ float qmaxf(float v) {
    v = fmaxf(v, __shfl_xor_sync(0xffffffffu, v, 1));
    v = fmaxf(v, __shfl_xor_sync(0xffffffffu, v, 2));
    return v;
}
__device__ __forceinline__ float qsumf(float v) {
    v += __shfl_xor_sync(0xffffffffu, v, 1);
    v += __shfl_xor_sync(0xffffffffu, v, 2);
    return v;
}
#define CP16(dst, src) asm volatile("cp.async.cg.shared.global [%0], [%1], 16;" :: "r"(dst), "l"(src))
#define CPCOMMIT()     asm volatile("cp.async.commit_group;" ::: "memory")
#define CPWAIT0()      asm volatile("cp.async.wait_group 0;" ::: "memory")

// ---------------- K0: gather sampled keys (fp32 + packed bf16) ----------------
__global__ void k_gather(const float* __restrict__ keys, const int* __restrict__ sidx) {
    int bh = blockIdx.x;
    for (int i = threadIdx.x; i < 48 * 32; i += 256) {
        int u = i >> 5, c2 = i & 31;
        float2 v = make_float2(0.f, 0.f);
        if (u < UU) {
            v = *(const float2*)&keys[((size_t)bh * SK + sidx[u]) * DIM + 2 * c2];
            *(float2*)&g_Ksamp[(bh * UU + u) * DIM + 2 * c2] = v;
        }
        g_Ksb[bh * 48 * 32 + i] = packbf(v.x, v.y);
    }
}

// ---------------- K1: M-tilde via single bf16 GEMM ----------------
__global__ __launch_bounds__(256) void k_Mb(const float* __restrict__ q) {
    __shared__ unsigned Qb[128 * 36];
    __shared__ unsigned Ksb[48 * 36];
    int bh = blockIdx.x, l0 = blockIdx.y * 128;
    int tid = threadIdx.x, w = tid >> 5, lane = tid & 31;
    int lq = lane >> 2, lr = lane & 3, mi = lane >> 3, mrow = lane & 7;

    const float4* qb4 = (const float4*)(q + ((size_t)bh * LQ + l0) * DIM);
    for (int i = tid; i < 128 * 16; i += 256) {
        int r = i >> 4, cb = i & 15;
        float4 f = qb4[i];
        *(uint2*)&Qb[r * 36 + 2 * cb] = make_uint2(packbf(f.x, f.y), packbf(f.z, f.w));
    }
    for (int i = tid; i < 48 * 32; i += 256) {
        int r = i >> 5, c2 = i & 31;
        Ksb[r * 36 + c2] = g_Ksb[bh * 48 * 32 + i];
    }
    __syncthreads();

    unsigned qbase = su32(Qb), kbase = su32(Ksb);
    unsigned aq[4][4];
#pragma unroll
    for (int ks = 0; ks < 4; ks++) {
        unsigned a = qbase + ((16 * w + (mi & 1) * 8 + mrow) * 36 + 8 * ks + (mi >> 1) * 4) * 4;
        ldm4(aq[ks][0], aq[ks][1], aq[ks][2], aq[ks][3], a);
    }

    float C[6][4];
#pragma unroll
    for (int n = 0; n < 6; n++) { C[n][0] = C[n][1] = C[n][2] = C[n][3] = 0.f; }
#pragma unroll
    for (int ks = 0; ks < 4; ks++) {
#pragma unroll
        for (int nt2 = 0; nt2 < 3; nt2++) {
            unsigned b0, b1, b2, b3;
            unsigned a = kbase + ((16 * nt2 + (mi & 1) * 8 + mrow) * 36 + 8 * ks + (mi >> 1) * 4) * 4;
            ldm4(b0, b1, b2, b3, a);
            mma16(C[2 * nt2],     aq[ks], b0, b2);
            mma16(C[2 * nt2 + 1], aq[ks], b1, b3);
        }
    }

    float mx0 = -1e30f, mx1 = -1e30f, sm0 = 0.f, sm1 = 0.f;
#pragma unroll
    for (int nt = 0; nt < 6; nt++) {
        int c = 8 * nt + 2 * lr;
        sm0 += C[nt][0] + C[nt][1];
        sm1 += C[nt][2] + C[nt][3];
        if (c < UU)     { mx0 = fmaxf(mx0, C[nt][0]); mx1 = fmaxf(mx1, C[nt][2]); }
        if (c + 1 < UU) { mx0 = fmaxf(mx0, C[nt][1]); mx1 = fmaxf(mx1, C[nt][3]); }
    }
    mx0 = qmaxf(mx0); mx1 = qmaxf(mx1); sm0 = qsumf(sm0); sm1 = qsumf(sm1);
    if (lr == 0) {
        g_M[bh * LQ + l0 + 16 * w + lq]     = mx0 - sm0 * (1.0f / SK);
        g_M[bh * LQ + l0 + 16 * w + lq + 8] = mx1 - sm1 * (1.0f / SK);
    }
}

// ---------------- K2: bisection threshold + exact recompute + bitonic top-45 ----------------
__global__ __launch_bounds__(256) void k_sel(const float* __restrict__ q) {
    extern __shared__ float dsm[];
    float* Ks = dsm;                       // 45*64
    float* D  = Ks + UU * DIM;             // CAP*48
    __shared__ float redA[8], redB[8];
    __shared__ int   icnt[8];
    __shared__ unsigned long long skey[256];
    __shared__ int   candIdx[CAP];
    __shared__ float Mex[CAP];
    __shared__ int   sidx[UU];
    __shared__ int   cnt;
    __shared__ float bc[2];

    int bh = blockIdx.x, tid = threadIdx.x, w = tid >> 5, lane = tid & 31;

    float v[16];
#pragma unroll
    for (int j = 0; j < 16; j++) v[j] = g_M[bh * LQ + tid + 256 * j];
    if (tid == 0) cnt = 0;

    // ---- min/max of M-tilde ----
    float mn = v[0], mx = v[0];
#pragma unroll
    for (int j = 1; j < 16; j++) { mn = fminf(mn, v[j]); mx = fmaxf(mx, v[j]); }
#pragma unroll
    for (int off = 16; off; off >>= 1) {
        mn = fminf(mn, __shfl_xor_sync(0xffffffffu, mn, off));
        mx = fmaxf(mx, __shfl_xor_sync(0xffffffffu, mx, off));
    }
    if (lane == 0) { redA[w] = mn; redB[w] = mx; }
    __syncthreads();
    if (tid == 0) {
        float a = redA[0], b = redB[0];
#pragma unroll
        for (int i = 1; i < 8; i++) { a = fminf(a, redA[i]); b = fmaxf(b, redB[i]); }
        bc[0] = a; bc[1] = b;
    }
    __syncthreads();

    // ---- bisection: invariant count(>=lo) >= UU > count(>=hi) ----
    float lo = bc[0], hi = bc[1] + 1.0f;
    for (int it = 0; it < 22; it++) {
        float mid = 0.5f * (lo + hi);
        int c = 0;
#pragma unroll
        for (int j = 0; j < 16; j++) c += (v[j] >= mid) ? 1 : 0;
#pragma unroll
        for (int off = 16; off; off >>= 1) c += __shfl_xor_sync(0xffffffffu, c, off);
        if (lane == 0) icnt[w] = c;
        __syncthreads();
        int tot = icnt[0] + icnt[1] + icnt[2] + icnt[3] +
                  icnt[4] + icnt[5] + icnt[6] + icnt[7];
        if (tot >= UU) lo = mid; else hi = mid;
        __syncthreads();
    }
    float thr = lo - MARGIN;

    // ---- compact candidates ----
#pragma unroll
    for (int j = 0; j < 16; j++) {
        if (v[j] >= thr) {
            int pos = atomicAdd(&cnt, 1);
            if (pos < CAP) candIdx[pos] = tid + 256 * j;
        }
    }
    for (int i = tid; i < UU * DIM; i += 256) Ks[i] = g_Ksamp[bh * UU * DIM + i];
    __syncthreads();
    int ccnt = min(cnt, CAP);

    // ---- exact fp32 dots ----
    int total = ccnt * UU;
    for (int p = tid; p < total; p += 256) {
        int c = p / UU, k = p - c * UU;
        const float4* qr = (const float4*)(q + ((size_t)bh * LQ + candIdx[c]) * DIM);
        const float4* kr = (const float4*)(Ks + k * DIM);
        float acc = 0.f;
#pragma unroll
        for (int d4 = 0; d4 < 16; d4++) {
            float4 a = qr[d4], b = kr[d4];
            acc += a.x * b.x + a.y * b.y + a.z * b.z + a.w * b.w;
        }
        D[c * 48 + k] = acc;
    }
    __syncthreads();

    // ---- exact M per candidate ----
    for (int c = tid; c < ccnt; c += 256) {
        float mxv = -1e30f, smv = 0.f;
#pragma unroll 5
        for (int k = 0; k < UU; k++) {
            float x = D[c * 48 + k];
            mxv = fmaxf(mxv, x); smv += x;
        }
        Mex[c] = mxv - smv * (1.0f / SK);
    }
    __syncthreads();

    // ---- bitonic sort 256 keys: value desc, index asc ----
    unsigned long long key = ~0ull;
    if (tid < ccnt) {
        unsigned u = __float_as_uint(Mex[tid]);
        u = (u & 0x80000000u) ? ~u : (u | 0x80000000u);   // ascending order map
        key = ((unsigned long long)(~u) << 32) | (unsigned)candIdx[tid];
    }
    skey[tid] = key;
    __syncthreads();
#pragma unroll
    for (int k = 2; k <= 256; k <<= 1) {
#pragma unroll
        for (int j = k >> 1; j > 0; j >>= 1) {
            int p = tid ^ j;
            if (p > tid) {
                unsigned long long a = skey[tid], b = skey[p];
                bool up = ((tid & k) == 0);
                if (up ? (a > b) : (a < b)) { skey[tid] = b; skey[p] = a; }
            }
            __syncthreads();
        }
    }
    if (tid < UU) sidx[tid] = (int)(unsigned)(skey[tid] & 0xffffffffu);
    __syncthreads();

    // ---- write indices + pack Q_reduce bf16 (pre-scaled) ----
    for (int i = tid; i < UU; i += 256) g_topidx[bh * UU + i] = sidx[i];
    for (int i = tid; i < UU * 32; i += 256) {
        int u = i >> 5, c2 = i & 31;
        float2 qv = *(const float2*)&q[((size_t)bh * LQ + sidx[u]) * DIM + 2 * c2];
        g_Qbf[(bh * UU + u) * 32 + c2] = packbf(qv.x * 0.125f, qv.y * 0.125f);
    }
}

// ---------------- K3: fused bf16 flash attention, cp.async V pipeline ----------------
// smem: [P (alias Q) 64*68 | Ksu 128*36 | Vsu 128*36 | Vstage 8192 f32]
__global__ __launch_bounds__(256, 2) void k_attn(const float* __restrict__ K,
                                                 const float* __restrict__ V) {
    extern __shared__ unsigned dynu[];
    unsigned* Pu  = dynu;                   // 64*68 (Q lives here during prologue)
    unsigned* Qsu = dynu;
    unsigned* Ksu = dynu + 64 * 68;         // 128*36
    unsigned* Vsu = Ksu + 128 * 36;         // 128*36
    float*    Vst = (float*)(Vsu + 128 * 36); // 128*64 f32 stage

    int bh = blockIdx.x, sp = blockIdx.y;
    int tid = threadIdx.x, w = tid >> 5, lane = tid & 31;
    int rg = w & 3, kh = w >> 2, lq = lane >> 2, lr = lane & 3;
    int mi = lane >> 3, mrow = lane & 7;

    unsigned vst_s = su32(Vst);
    const float* vg = V + ((size_t)bh * SK + (size_t)sp * 512) * DIM;

    // prologue: start async copy of V tile 0
#pragma unroll
    for (int c = 0; c < 8; c++)
        CP16(vst_s + (unsigned)(tid + 256 * c) * 16u, vg + (size_t)(tid + 256 * c) * 4);
    CPCOMMIT();

    // fill Q tile
    for (int i = tid; i < 64 * 32; i += 256) {
        int r = i >> 5, c2 = i & 31;
        Qsu[r * 36 + c2] = (r < UU) ? g_Qbf[(bh * UU + r) * 32 + c2] : 0u;
    }
    __syncthreads();

    unsigned qbase = su32(Qsu);
    unsigned aq[4][4];
#pragma unroll
    for (int ks = 0; ks < 4; ks++) {
        unsigned a = qbase + ((16 * rg + (mi & 1) * 8 + mrow) * 36 + 8 * ks + (mi >> 1) * 4) * 4;
        ldm4(aq[ks][0], aq[ks][1], aq[ks][2], aq[ks][3], a);
    }

    unsigned kbase = su32(Ksu), vbase = su32(Vsu), pbase = su32(Pu);

    float O[8][4];
#pragma unroll
    for (int n = 0; n < 8; n++) { O[n][0] = O[n][1] = O[n][2] = O[n][3] = 0.f; }
    float m0 = -1e30f, m1 = -1e30f, l0a = 0.f, l1a = 0.f;
    float4 vacc = make_float4(0.f, 0.f, 0.f, 0.f);

    for (int t = 0; t < 4; t++) {
        // early K loads (latency overlaps cp.async wait)
        const float4* kb = (const float4*)(K + ((size_t)bh * SK + (size_t)sp * 512 + t * 128) * DIM);
        float4 kr[8];
#pragma unroll
        for (int it = 0; it < 8; it++) kr[it] = kb[tid + it * 256];

        CPWAIT0();
        __syncthreads();                   // V stage ready; prior compute done

        // convert V stage -> bf16 + fp32 colsum (same word mapping as cp.async)
        {
            const float4* st4 = (const float4*)Vst;
#pragma unroll
            for (int c = 0; c < 8; c++) {
                int i = tid + 256 * c;
                float4 g = st4[i];
                vacc.x += g.x; vacc.y += g.y; vacc.z += g.z; vacc.w += g.w;
                int r = i >> 4, cb = i & 15;
                *(uint2*)&Vsu[r * 36 + 2 * cb] = make_uint2(packbf(g.x, g.y), packbf(g.z, g.w));
            }
        }
        // prefetch next V tile into stage (safe: each thread overwrites only words it read)
        if (t < 3) {
            const float* src = vg + (size_t)(t + 1) * 128 * DIM;
#pragma unroll
            for (int c = 0; c < 8; c++)
                CP16(vst_s + (unsigned)(tid + 256 * c) * 16u, src + (size_t)(tid + 256 * c) * 4);
            CPCOMMIT();
        }
        // convert K regs -> bf16
#pragma unroll
        for (int it = 0; it < 8; it++) {
            int i = tid + it * 256;
            int r = i >> 4, cb = i & 15;
            float4 f = kr[it];
            *(uint2*)&Ksu[r * 36 + 2 * cb] = make_uint2(packbf(f.x, f.y), packbf(f.z, f.w));
        }
        __syncthreads();

        // S = Q @ K^T
        float C[8][4];
#pragma unroll
        for (int n = 0; n < 8; n++) { C[n][0] = C[n][1] = C[n][2] = C[n][3] = 0.f; }
#pragma unroll
        for (int ks = 0; ks < 4; ks++) {
#pragma unroll
            for (int nt2 = 0; nt2 < 4; nt2++) {
                unsigned b0, b1, b2, b3;
                unsigned a = kbase + ((64 * kh + 16 * nt2 + (mi & 1) * 8 + mrow) * 36 +
                                      8 * ks + (mi >> 1) * 4) * 4;
                ldm4(b0, b1, b2, b3, a);
                mma16(C[2 * nt2],     aq[ks], b0, b2);
                mma16(C[2 * nt2 + 1], aq[ks], b1, b3);
            }
        }

        // online softmax
        float tm0 = -1e30f, tm1 = -1e30f;
#pragma unroll
        for (int nt = 0; nt < 8; nt++) {
            tm0 = fmaxf(tm0, fmaxf(C[nt][0], C[nt][1]));
            tm1 = fmaxf(tm1, fmaxf(C[nt][2], C[nt][3]));
        }
        tm0 = qmaxf(tm0); tm1 = qmaxf(tm1);
        float nm0 = fmaxf(m0, tm0), nm1 = fmaxf(m1, tm1);
        float f0 = __expf(m0 - nm0), f1 = __expf(m1 - nm1);
        float rs0 = 0.f, rs1 = 0.f;
#pragma unroll
        for (int nt = 0; nt < 8; nt++) {
            C[nt][0] = __expf(C[nt][0] - nm0); C[nt][1] = __expf(C[nt][1] - nm0);
            C[nt][2] = __expf(C[nt][2] - nm1); C[nt][3] = __expf(C[nt][3] - nm1);
            rs0 += C[nt][0] + C[nt][1]; rs1 += C[nt][2] + C[nt][3];
            O[nt][0] *= f0; O[nt][1] *= f0; O[nt][2] *= f1; O[nt][3] *= f1;
        }
        rs0 = qsumf(rs0); rs1 = qsumf(rs1);
        l0a = l0a * f0 + rs0; l1a = l1a * f1 + rs1;
        m0 = nm0; m1 = nm1;

        // P -> smem bf16 (warp-private cells)
        {
            int rb0 = (16 * rg + lq) * 68 + 32 * kh + lr;
            int rb1 = rb0 + 8 * 68;
#pragma unroll
            for (int nt = 0; nt < 8; nt++) {
                Pu[rb0 + 4 * nt] = packbf(C[nt][0], C[nt][1]);
                Pu[rb1 + 4 * nt] = packbf(C[nt][2], C[nt][3]);
            }
        }
        __syncwarp();

        // O += P @ V
#pragma unroll
        for (int ks = 0; ks < 4; ks++) {
            unsigned ap[4];
            unsigned a = pbase + ((16 * rg + (mi & 1) * 8 + mrow) * 68 +
                                  32 * kh + 8 * ks + (mi >> 1) * 4) * 4;
            ldm4(ap[0], ap[1], ap[2], ap[3], a);
#pragma unroll
            for (int nd2 = 0; nd2 < 4; nd2++) {
                unsigned b0, b1, b2, b3;
                unsigned vb_a = vbase + ((64 * kh + 16 * ks + (mi & 1) * 8 + mrow) * 36 +
                                         8 * nd2 + (mi >> 1) * 4) * 4;
                ldm4t(b0, b1, b2, b3, vb_a);
                mma16(O[2 * nd2],     ap, b0, b1);
                mma16(O[2 * nd2 + 1], ap, b2, b3);
            }
        }
    }

    // fp32 V colsum exchange (reuse P region; compute done)
    float4* sm4 = (float4*)dynu;
    __syncthreads();
    sm4[tid] = vacc;
    __syncthreads();
    if (tid < 64) {
        int g = tid >> 2, j = tid & 3;
        float s = 0.f;
#pragma unroll
        for (int tt = 0; tt < 16; tt++) {
            const float* p4 = (const float*)&sm4[g + 16 * tt];
            s += p4[j];
        }
        g_Vpart[(bh * NS + sp) * DIM + tid] = s;
    }

    // store partials (p = 2*sp + kh)
    int p = sp * 2 + kh;
    int r0 = 16 * rg + lq, r1 = r0 + 8;
    if (r0 < UU) {
        float* dst = &g_actx[((bh * 16 + p) * UU + r0) * DIM];
#pragma unroll
        for (int nt = 0; nt < 8; nt++)
            *(float2*)&dst[8 * nt + 2 * lr] = make_float2(O[nt][0], O[nt][1]);
        if (lr == 0) g_aml[(bh * 16 + p) * UU + r0] = make_float2(m0, l0a);
    }
    if (r1 < UU) {
        float* dst = &g_actx[((bh * 16 + p) * UU + r1) * DIM];
#pragma unroll
        for (int nt = 0; nt < 8; nt++)
            *(float2*)&dst[8 * nt + 2 * lr] = make_float2(O[nt][2], O[nt][3]);
        if (lr == 0) g_aml[(bh * 16 + p) * UU + r1] = make_float2(m1, l1a);
    }
}

// ---------------- K4: broadcast V_sum into entire output ----------------
__global__ void k_fill(float* __restrict__ out) {
    __shared__ float sv[64];
    int bh = blockIdx.x, ry = blockIdx.y, tid = threadIdx.x;
    if (tid < 64) {
        float s = 0.f;
#pragma unroll
        for (int sp = 0; sp < NS; sp++) s += g_Vpart[(bh * NS + sp) * DIM + tid];
        sv[tid] = s;
    }
    __syncthreads();
    float4* o4 = (float4*)(out + ((size_t)bh * LQ + (size_t)ry * 128) * DIM);
    float4 val = ((const float4*)sv)[tid & 15];
    for (int i = tid; i < 128 * 16; i += 256) o4[i] = val;
}

// ---------------- K5: merge 16 partials, normalize, scatter ----------------
__global__ void k_combine(float* __restrict__ out) {
    __shared__ float wgt[UU * 16];
    __shared__ float Lr[UU];
    __shared__ int   idx[UU];
    int bh = blockIdx.x, tid = threadIdx.x;
    if (tid < UU) {
        float2 ml[16]; float mg = -1e30f;
#pragma unroll
        for (int p = 0; p < 16; p++) {
            ml[p] = g_aml[(bh * 16 + p) * UU + tid];
            mg = fmaxf(mg, ml[p].x);
        }
        float L = 0.f;
#pragma unroll
        for (int p = 0; p < 16; p++) {
            float wv = __expf(ml[p].x - mg);
            wgt[tid * 16 + p] = wv;
            L += wv * ml[p].y;
        }
        Lr[tid] = L;
        idx[tid] = g_topidx[bh * UU + tid];
    }
    __syncthreads();
    for (int i = tid; i < UU * DIM; i += 256) {
        int u = i >> 6, d = i & 63;
        float s = 0.f;
#pragma unroll
        for (int p = 0; p < 16; p++)
            s += wgt[u * 16 + p] * g_actx[((bh * 16 + p) * UU + u) * DIM + d];
        out[((size_t)bh * LQ + idx[u]) * DIM + d] = s / Lr[u];
    }
}

// ---------------- launch ----------------
#define ATTN_SMEM ((64 * 68 + 128 * 36 + 128 * 36 + 8192) * 4)
#define SEL_SMEM  ((UU * DIM + CAP * 48) * 4)

extern "C" void kernel_launch(void* const* d_in, const int* in_sizes, int n_in,
                              void* d_out, int out_size) {
    const float* q    = (const float*)d_in[0];
    const float* keys = (const float*)d_in[1];
    const float* vals = (const float*)d_in[2];
    const int*   sidx = (const int*)d_in[3];
    float* out = (float*)d_out;

    cudaFuncSetAttribute(k_attn, cudaFuncAttributeMaxDynamicSharedMemorySize, ATTN_SMEM);
    cudaFuncSetAttribute(k_sel,  cudaFuncAttributeMaxDynamicSharedMemorySize, SEL_SMEM);

    k_gather<<<BH, 256>>>(keys, sidx);
    k_Mb<<<dim3(BH, LQ / 128), 256>>>(q);
    k_sel<<<BH, 256, SEL_SMEM>>>(q);
    k_attn<<<dim3(BH, NS), 256, ATTN_SMEM>>>(keys, vals);
    k_fill<<<dim3(BH, LQ / 128), 256>>>(out);
    k_combine<<<BH, 256>>>(out);
}

// round 9
// speedup vs baseline: 3.7642x; 1.0429x over previous
#include <cuda_runtime.h>
#include <cuda_bf16.h>

#define BH   128
#define LQ   4096
#define SK   4096
#define DIM  64
#define UU   45
#define NS   8
#define CAP  160
#define MARGIN 0.4f

// ---------------- scratch ----------------
__device__ float    g_M[BH * LQ];
__device__ int      g_topidx[BH * UU];
__device__ float    g_Ksamp[BH * UU * DIM];
__device__ unsigned g_Ksb[BH * 48 * 32];
__device__ unsigned g_Qbf[BH * UU * 32];
__device__ float    g_Vpart[BH * NS * DIM];
__device__ float    g_actx[BH * 16 * UU * DIM];
__device__ float2   g_aml[BH * 16 * UU];

// ---------------- helpers ----------------
__device__ __forceinline__ unsigned packbf(float lo, float hi) {
    unsigned u; asm("cvt.rn.bf16x2.f32 %0, %1, %2;" : "=r"(u) : "f"(hi), "f"(lo)); return u;
}
__device__ __forceinline__ unsigned su32(const void* p) {
    unsigned a;
    asm("{ .reg .u64 t; cvta.to.shared.u64 t, %1; cvt.u32.u64 %0, t; }" : "=r"(a) : "l"(p));
    return a;
}
__device__ __forceinline__ void ldm4(unsigned& r0, unsigned& r1, unsigned& r2, unsigned& r3, unsigned a) {
    asm volatile("ldmatrix.sync.aligned.m8n8.x4.shared.b16 {%0,%1,%2,%3}, [%4];"
                 : "=r"(r0), "=r"(r1), "=r"(r2), "=r"(r3) : "r"(a));
}
__device__ __forceinline__ void ldm4t(unsigned& r0, unsigned& r1, unsigned& r2, unsigned& r3, unsigned a) {
    asm volatile("ldmatrix.sync.aligned.m8n8.x4.trans.shared.b16 {%0,%1,%2,%3}, [%4];"
                 : "=r"(r0), "=r"(r1), "=r"(r2), "=r"(r3) : "r"(a));
}
__device__ __forceinline__ void mma16(float* d, const unsigned* a, unsigned b0, unsigned b1) {
    asm volatile("mma.sync.aligned.m16n8k16.row.col.f32.bf16.bf16.f32 "
                 "{%0,%1,%2,%3}, {%4,%5,%6,%7}, {%8,%9}, {%0,%1,%2,%3};"
                 : "+f"(d[0]), "+f"(d[1]), "+f"(d[2]), "+f"(d[3])
                 : "r"(a[0]), "r"(a[1]), "r"(a[2]), "r"(a[3]), "r"(b0), "r"(b1));
}
__device__ __forceinline__ float qmaxf(float v) {
    v = fmaxf(v, __shfl_xor_sync(0xffffffffu, v, 1));
    v = fmaxf(v, __shfl_xor_sync(0xffffffffu, v, 2));
    return v;
}
__device__ __forceinline__ float qsumf(float v) {
    v += __shfl_xor_sync(0xffffffffu, v, 1);
    v += __shfl_xor_sync(0xffffffffu, v, 2);
    return v;
}
#define CP16(dst, src) asm volatile("cp.async.cg.shared.global [%0], [%1], 16;" :: "r"(dst), "l"(src))
#define CPCOMMIT()     asm volatile("cp.async.commit_group;" ::: "memory")
#define CPWAIT0()      asm volatile("cp.async.wait_group 0;" ::: "memory")

// ---------------- K0: gather sampled keys (fp32 + packed bf16) ----------------
__global__ void k_gather(const float* __restrict__ keys, const int* __restrict__ sidx) {
    int bh = blockIdx.x;
    for (int i = threadIdx.x; i < 48 * 32; i += 256) {
        int u = i >> 5, c2 = i & 31;
        float2 v = make_float2(0.f, 0.f);
        if (u < UU) {
            v = *(const float2*)&keys[((size_t)bh * SK + sidx[u]) * DIM + 2 * c2];
            *(float2*)&g_Ksamp[(bh * UU + u) * DIM + 2 * c2] = v;
        }
        g_Ksb[bh * 48 * 32 + i] = packbf(v.x, v.y);
    }
}

// ---------------- K1: M-tilde via single bf16 GEMM ----------------
__global__ __launch_bounds__(256) void k_Mb(const float* __restrict__ q) {
    __shared__ unsigned Qb[128 * 36];
    __shared__ unsigned Ksb[48 * 36];
    int bh = blockIdx.x, l0 = blockIdx.y * 128;
    int tid = threadIdx.x, w = tid >> 5, lane = tid & 31;
    int lq = lane >> 2, lr = lane & 3, mi = lane >> 3, mrow = lane & 7;

    const float4* qb4 = (const float4*)(q + ((size_t)bh * LQ + l0) * DIM);
    for (int i = tid; i < 128 * 16; i += 256) {
        int r = i >> 4, cb = i & 15;
        float4 f = qb4[i];
        *(uint2*)&Qb[r * 36 + 2 * cb] = make_uint2(packbf(f.x, f.y), packbf(f.z, f.w));
    }
    for (int i = tid; i < 48 * 32; i += 256) {
        int r = i >> 5, c2 = i & 31;
        Ksb[r * 36 + c2] = g_Ksb[bh * 48 * 32 + i];
    }
    __syncthreads();

    unsigned qbase = su32(Qb), kbase = su32(Ksb);
    unsigned aq[4][4];
#pragma unroll
    for (int ks = 0; ks < 4; ks++) {
        unsigned a = qbase + ((16 * w + (mi & 1) * 8 + mrow) * 36 + 8 * ks + (mi >> 1) * 4) * 4;
        ldm4(aq[ks][0], aq[ks][1], aq[ks][2], aq[ks][3], a);
    }

    float C[6][4];
#pragma unroll
    for (int n = 0; n < 6; n++) { C[n][0] = C[n][1] = C[n][2] = C[n][3] = 0.f; }
#pragma unroll
    for (int ks = 0; ks < 4; ks++) {
#pragma unroll
        for (int nt2 = 0; nt2 < 3; nt2++) {
            unsigned b0, b1, b2, b3;
            unsigned a = kbase + ((16 * nt2 + (mi & 1) * 8 + mrow) * 36 + 8 * ks + (mi >> 1) * 4) * 4;
            ldm4(b0, b1, b2, b3, a);
            mma16(C[2 * nt2],     aq[ks], b0, b2);
            mma16(C[2 * nt2 + 1], aq[ks], b1, b3);
        }
    }

    float mx0 = -1e30f, mx1 = -1e30f, sm0 = 0.f, sm1 = 0.f;
#pragma unroll
    for (int nt = 0; nt < 6; nt++) {
        int c = 8 * nt + 2 * lr;
        sm0 += C[nt][0] + C[nt][1];
        sm1 += C[nt][2] + C[nt][3];
        if (c < UU)     { mx0 = fmaxf(mx0, C[nt][0]); mx1 = fmaxf(mx1, C[nt][2]); }
        if (c + 1 < UU) { mx0 = fmaxf(mx0, C[nt][1]); mx1 = fmaxf(mx1, C[nt][3]); }
    }
    mx0 = qmaxf(mx0); mx1 = qmaxf(mx1); sm0 = qsumf(sm0); sm1 = qsumf(sm1);
    if (lr == 0) {
        g_M[bh * LQ + l0 + 16 * w + lq]     = mx0 - sm0 * (1.0f / SK);
        g_M[bh * LQ + l0 + 16 * w + lq + 8] = mx1 - sm1 * (1.0f / SK);
    }
}

// ---------------- K2: bisection threshold + exact recompute + bitonic top-45 ----------------
__global__ __launch_bounds__(256) void k_sel(const float* __restrict__ q) {
    extern __shared__ float dsm[];
    float* Ks = dsm;                       // 45*64
    float* D  = Ks + UU * DIM;             // CAP*48
    __shared__ float redA[8], redB[8];
    __shared__ int   icnt[8];
    __shared__ unsigned long long skey[256];
    __shared__ int   candIdx[CAP];
    __shared__ float Mex[CAP];
    __shared__ int   sidx[UU];
    __shared__ int   cnt;
    __shared__ float bc[2];

    int bh = blockIdx.x, tid = threadIdx.x, w = tid >> 5, lane = tid & 31;

    float v[16];
#pragma unroll
    for (int j = 0; j < 16; j++) v[j] = g_M[bh * LQ + tid + 256 * j];
    if (tid == 0) cnt = 0;

    float mn = v[0], mx = v[0];
#pragma unroll
    for (int j = 1; j < 16; j++) { mn = fminf(mn, v[j]); mx = fmaxf(mx, v[j]); }
#pragma unroll
    for (int off = 16; off; off >>= 1) {
        mn = fminf(mn, __shfl_xor_sync(0xffffffffu, mn, off));
        mx = fmaxf(mx, __shfl_xor_sync(0xffffffffu, mx, off));
    }
    if (lane == 0) { redA[w] = mn; redB[w] = mx; }
    __syncthreads();
    if (tid == 0) {
        float a = redA[0], b = redB[0];
#pragma unroll
        for (int i = 1; i < 8; i++) { a = fminf(a, redA[i]); b = fmaxf(b, redB[i]); }
        bc[0] = a; bc[1] = b;
    }
    __syncthreads();

    float lo = bc[0], hi = bc[1] + 1.0f;
    for (int it = 0; it < 22; it++) {
        float mid = 0.5f * (lo + hi);
        int c = 0;
#pragma unroll
        for (int j = 0; j < 16; j++) c += (v[j] >= mid) ? 1 : 0;
#pragma unroll
        for (int off = 16; off; off >>= 1) c += __shfl_xor_sync(0xffffffffu, c, off);
        if (lane == 0) icnt[w] = c;
        __syncthreads();
        int tot = icnt[0] + icnt[1] + icnt[2] + icnt[3] +
                  icnt[4] + icnt[5] + icnt[6] + icnt[7];
        if (tot >= UU) lo = mid; else hi = mid;
        __syncthreads();
    }
    float thr = lo - MARGIN;

#pragma unroll
    for (int j = 0; j < 16; j++) {
        if (v[j] >= thr) {
            int pos = atomicAdd(&cnt, 1);
            if (pos < CAP) candIdx[pos] = tid + 256 * j;
        }
    }
    for (int i = tid; i < UU * DIM; i += 256) Ks[i] = g_Ksamp[bh * UU * DIM + i];
    __syncthreads();
    int ccnt = min(cnt, CAP);

    int total = ccnt * UU;
    for (int p = tid; p < total; p += 256) {
        int c = p / UU, k = p - c * UU;
        const float4* qr = (const float4*)(q + ((size_t)bh * LQ + candIdx[c]) * DIM);
        const float4* kr = (const float4*)(Ks + k * DIM);
        float acc = 0.f;
#pragma unroll
        for (int d4 = 0; d4 < 16; d4++) {
            float4 a = qr[d4], b = kr[d4];
            acc += a.x * b.x + a.y * b.y + a.z * b.z + a.w * b.w;
        }
        D[c * 48 + k] = acc;
    }
    __syncthreads();

    for (int c = tid; c < ccnt; c += 256) {
        float mxv = -1e30f, smv = 0.f;
#pragma unroll 5
        for (int k = 0; k < UU; k++) {
            float x = D[c * 48 + k];
            mxv = fmaxf(mxv, x); smv += x;
        }
        Mex[c] = mxv - smv * (1.0f / SK);
    }
    __syncthreads();

    unsigned long long key = ~0ull;
    if (tid < ccnt) {
        unsigned u = __float_as_uint(Mex[tid]);
        u = (u & 0x80000000u) ? ~u : (u | 0x80000000u);
        key = ((unsigned long long)(~u) << 32) | (unsigned)candIdx[tid];
    }
    skey[tid] = key;
    __syncthreads();
#pragma unroll
    for (int k = 2; k <= 256; k <<= 1) {
#pragma unroll
        for (int j = k >> 1; j > 0; j >>= 1) {
            int p = tid ^ j;
            if (p > tid) {
                unsigned long long a = skey[tid], b = skey[p];
                bool up = ((tid & k) == 0);
                if (up ? (a > b) : (a < b)) { skey[tid] = b; skey[p] = a; }
            }
            __syncthreads();
        }
    }
    if (tid < UU) sidx[tid] = (int)(unsigned)(skey[tid] & 0xffffffffu);
    __syncthreads();

    for (int i = tid; i < UU; i += 256) g_topidx[bh * UU + i] = sidx[i];
    for (int i = tid; i < UU * 32; i += 256) {
        int u = i >> 5, c2 = i & 31;
        float2 qv = *(const float2*)&q[((size_t)bh * LQ + sidx[u]) * DIM + 2 * c2];
        g_Qbf[(bh * UU + u) * 32 + c2] = packbf(qv.x * 0.125f, qv.y * 0.125f);
    }
}

// ---------------- K3: fused bf16 flash attention, register-resident P,
//                      cp.async K+V single-stage prefetch ----------------
// smem: [Qsu 64*36 | Ksu 128*36 | Vsu 128*36 | Kst 8192 f32 | Vst 8192 f32]
__global__ __launch_bounds__(256, 2) void k_attn(const float* __restrict__ K,
                                                 const float* __restrict__ V) {
    extern __shared__ unsigned dynu[];
    unsigned* Qsu = dynu;                       // 64*36
    unsigned* Ksu = dynu + 64 * 36;             // 128*36
    unsigned* Vsu = Ksu + 128 * 36;             // 128*36
    float*    Kst = (float*)(Vsu + 128 * 36);   // 128*64 f32
    float*    Vst = Kst + 8192;                 // 128*64 f32

    int bh = blockIdx.x, sp = blockIdx.y;
    int tid = threadIdx.x, w = tid >> 5, lane = tid & 31;
    int rg = w & 3, kh = w >> 2, lq = lane >> 2, lr = lane & 3;
    int mi = lane >> 3, mrow = lane & 7;

    unsigned kst_s = su32(Kst), vst_s = su32(Vst);
    const float* kg = K + ((size_t)bh * SK + (size_t)sp * 512) * DIM;
    const float* vg = V + ((size_t)bh * SK + (size_t)sp * 512) * DIM;

    // prologue: async copy K(0), V(0)
#pragma unroll
    for (int c = 0; c < 8; c++) {
        CP16(kst_s + (unsigned)(tid + 256 * c) * 16u, kg + (size_t)(tid + 256 * c) * 4);
        CP16(vst_s + (unsigned)(tid + 256 * c) * 16u, vg + (size_t)(tid + 256 * c) * 4);
    }
    CPCOMMIT();

    // fill Q tile
    for (int i = tid; i < 64 * 32; i += 256) {
        int r = i >> 5, c2 = i & 31;
        Qsu[r * 36 + c2] = (r < UU) ? g_Qbf[(bh * UU + r) * 32 + c2] : 0u;
    }
    __syncthreads();

    unsigned qbase = su32(Qsu);
    unsigned aq[4][4];
#pragma unroll
    for (int ks = 0; ks < 4; ks++) {
        unsigned a = qbase + ((16 * rg + (mi & 1) * 8 + mrow) * 36 + 8 * ks + (mi >> 1) * 4) * 4;
        ldm4(aq[ks][0], aq[ks][1], aq[ks][2], aq[ks][3], a);
    }

    unsigned kbase = su32(Ksu), vbase = su32(Vsu);

    float O[8][4];
#pragma unroll
    for (int n = 0; n < 8; n++) { O[n][0] = O[n][1] = O[n][2] = O[n][3] = 0.f; }
    float m0 = -1e30f, m1 = -1e30f, l0a = 0.f, l1a = 0.f;
    float4 vacc = make_float4(0.f, 0.f, 0.f, 0.f);

    for (int t = 0; t < 4; t++) {
        CPWAIT0();
        __syncthreads();                  // stages ready; prior tile reads done

        // convert stages -> bf16 tiles (+ fp32 V colsum); same-thread word mapping
        {
            const float4* kst4 = (const float4*)Kst;
            const float4* vst4 = (const float4*)Vst;
#pragma unroll
            for (int c = 0; c < 8; c++) {
                int i = tid + 256 * c;
                int r = i >> 4, cb = i & 15;
                float4 f = kst4[i];
                *(uint2*)&Ksu[r * 36 + 2 * cb] = make_uint2(packbf(f.x, f.y), packbf(f.z, f.w));
                float4 g = vst4[i];
                vacc.x += g.x; vacc.y += g.y; vacc.z += g.z; vacc.w += g.w;
                *(uint2*)&Vsu[r * 36 + 2 * cb] = make_uint2(packbf(g.x, g.y), packbf(g.z, g.w));
            }
        }
        __syncthreads();                  // tiles visible; stage reads complete

        // prefetch next tile into stages (lands during compute)
        if (t < 3) {
            const float* ksrc = kg + (size_t)(t + 1) * 128 * DIM;
            const float* vsrc = vg + (size_t)(t + 1) * 128 * DIM;
#pragma unroll
            for (int c = 0; c < 8; c++) {
                CP16(kst_s + (unsigned)(tid + 256 * c) * 16u, ksrc + (size_t)(tid + 256 * c) * 4);
                CP16(vst_s + (unsigned)(tid + 256 * c) * 16u, vsrc + (size_t)(tid + 256 * c) * 4);
            }
            CPCOMMIT();
        }

        // S = Q @ K^T  (warp: 16 q rows x its 64-key half)
        float C[8][4];
#pragma unroll
        for (int n = 0; n < 8; n++) { C[n][0] = C[n][1] = C[n][2] = C[n][3] = 0.f; }
#pragma unroll
        for (int ks = 0; ks < 4; ks++) {
#pragma unroll
            for (int nt2 = 0; nt2 < 4; nt2++) {
                unsigned b0, b1, b2, b3;
                unsigned a = kbase + ((64 * kh + 16 * nt2 + (mi & 1) * 8 + mrow) * 36 +
                                      8 * ks + (mi >> 1) * 4) * 4;
                ldm4(b0, b1, b2, b3, a);
                mma16(C[2 * nt2],     aq[ks], b0, b2);
                mma16(C[2 * nt2 + 1], aq[ks], b1, b3);
            }
        }

        // online softmax (rows lq, lq+8)
        float tm0 = -1e30f, tm1 = -1e30f;
#pragma unroll
        for (int nt = 0; nt < 8; nt++) {
            tm0 = fmaxf(tm0, fmaxf(C[nt][0], C[nt][1]));
            tm1 = fmaxf(tm1, fmaxf(C[nt][2], C[nt][3]));
        }
        tm0 = qmaxf(tm0); tm1 = qmaxf(tm1);
        float nm0 = fmaxf(m0, tm0), nm1 = fmaxf(m1, tm1);
        float f0 = __expf(m0 - nm0), f1 = __expf(m1 - nm1);
        float rs0 = 0.f, rs1 = 0.f;
#pragma unroll
        for (int nt = 0; nt < 8; nt++) {
            C[nt][0] = __expf(C[nt][0] - nm0); C[nt][1] = __expf(C[nt][1] - nm0);
            C[nt][2] = __expf(C[nt][2] - nm1); C[nt][3] = __expf(C[nt][3] - nm1);
            rs0 += C[nt][0] + C[nt][1]; rs1 += C[nt][2] + C[nt][3];
            O[nt][0] *= f0; O[nt][1] *= f0; O[nt][2] *= f1; O[nt][3] *= f1;
        }
        rs0 = qsumf(rs0); rs1 = qsumf(rs1);
        l0a = l0a * f0 + rs0; l1a = l1a * f1 + rs1;
        m0 = nm0; m1 = nm1;

        // O += P @ V — P stays in registers (C fragment == A fragment)
#pragma unroll
        for (int ks = 0; ks < 4; ks++) {
            unsigned ap[4];
            ap[0] = packbf(C[2 * ks][0],     C[2 * ks][1]);
            ap[1] = packbf(C[2 * ks][2],     C[2 * ks][3]);
            ap[2] = packbf(C[2 * ks + 1][0], C[2 * ks + 1][1]);
            ap[3] = packbf(C[2 * ks + 1][2], C[2 * ks + 1][3]);
#pragma unroll
            for (int nd2 = 0; nd2 < 4; nd2++) {
                unsigned b0, b1, b2, b3;
                unsigned vb_a = vbase + ((64 * kh + 16 * ks + (mi & 1) * 8 + mrow) * 36 +
                                         8 * nd2 + (mi >> 1) * 4) * 4;
                ldm4t(b0, b1, b2, b3, vb_a);
                mma16(O[2 * nd2],     ap, b0, b1);
                mma16(O[2 * nd2 + 1], ap, b2, b3);
            }
        }
    }

    // fp32 V colsum exchange (Q region free)
    float4* sm4 = (float4*)dynu;
    __syncthreads();
    sm4[tid] = vacc;
    __syncthreads();
    if (tid < 64) {
        int g = tid >> 2, j = tid & 3;
        float s = 0.f;
#pragma unroll
        for (int tt = 0; tt < 16; tt++) {
            const float* p4 = (const float*)&sm4[g + 16 * tt];
            s += p4[j];
        }
        g_Vpart[(bh * NS + sp) * DIM + tid] = s;
    }

    // store partials (p = 2*sp + kh)
    int p = sp * 2 + kh;
    int r0 = 16 * rg + lq, r1 = r0 + 8;
    if (r0 < UU) {
        float* dst = &g_actx[((bh * 16 + p) * UU + r0) * DIM];
#pragma unroll
        for (int nt = 0; nt < 8; nt++)
            *(float2*)&dst[8 * nt + 2 * lr] = make_float2(O[nt][0], O[nt][1]);
        if (lr == 0) g_aml[(bh * 16 + p) * UU + r0] = make_float2(m0, l0a);
    }
    if (r1 < UU) {
        float* dst = &g_actx[((bh * 16 + p) * UU + r1) * DIM];
#pragma unroll
        for (int nt = 0; nt < 8; nt++)
            *(float2*)&dst[8 * nt + 2 * lr] = make_float2(O[nt][2], O[nt][3]);
        if (lr == 0) g_aml[(bh * 16 + p) * UU + r1] = make_float2(m1, l1a);
    }
}

// ---------------- K4: broadcast V_sum into entire output ----------------
__global__ void k_fill(float* __restrict__ out) {
    __shared__ float sv[64];
    int bh = blockIdx.x, ry = blockIdx.y, tid = threadIdx.x;
    if (tid < 64) {
        float s = 0.f;
#pragma unroll
        for (int sp = 0; sp < NS; sp++) s += g_Vpart[(bh * NS + sp) * DIM + tid];
        sv[tid] = s;
    }
    __syncthreads();
    float4* o4 = (float4*)(out + ((size_t)bh * LQ + (size_t)ry * 128) * DIM);
    float4 val = ((const float4*)sv)[tid & 15];
    for (int i = tid; i < 128 * 16; i += 256) o4[i] = val;
}

// ---------------- K5: merge 16 partials, normalize, scatter ----------------
__global__ void k_combine(float* __restrict__ out) {
    __shared__ float wgt[UU * 16];
    __shared__ float Lr[UU];
    __shared__ int   idx[UU];
    int bh = blockIdx.x, tid = threadIdx.x;
    if (tid < UU) {
        float2 ml[16]; float mg = -1e30f;
#pragma unroll
        for (int p = 0; p < 16; p++) {
            ml[p] = g_aml[(bh * 16 + p) * UU + tid];
            mg = fmaxf(mg, ml[p].x);
        }
        float L = 0.f;
#pragma unroll
        for (int p = 0; p < 16; p++) {
            float wv = __expf(ml[p].x - mg);
            wgt[tid * 16 + p] = wv;
            L += wv * ml[p].y;
        }
        Lr[tid] = L;
        idx[tid] = g_topidx[bh * UU + tid];
    }
    __syncthreads();
    for (int i = tid; i < UU * DIM; i += 256) {
        int u = i >> 6, d = i & 63;
        float s = 0.f;
#pragma unroll
        for (int p = 0; p < 16; p++)
            s += wgt[u * 16 + p] * g_actx[((bh * 16 + p) * UU + u) * DIM + d];
        out[((size_t)bh * LQ + idx[u]) * DIM + d] = s / Lr[u];
    }
}

// ---------------- launch ----------------
#define ATTN_SMEM ((64 * 36 + 128 * 36 + 128 * 36 + 8192 + 8192) * 4)
#define SEL_SMEM  ((UU * DIM + CAP * 48) * 4)

extern "C" void kernel_launch(void* const* d_in, const int* in_sizes, int n_in,
                              void* d_out, int out_size) {
    const float* q    = (const float*)d_in[0];
    const float* keys = (const float*)d_in[1];
    const float* vals = (const float*)d_in[2];
    const int*   sidx = (const int*)d_in[3];
    float* out = (float*)d_out;

    cudaFuncSetAttribute(k_attn, cudaFuncAttributeMaxDynamicSharedMemorySize, ATTN_SMEM);
    cudaFuncSetAttribute(k_sel,  cudaFuncAttributeMaxDynamicSharedMemorySize, SEL_SMEM);

    k_gather<<<BH, 256>>>(keys, sidx);
    k_Mb<<<dim3(BH, LQ / 128), 256>>>(q);
    k_sel<<<BH, 256, SEL_SMEM>>>(q);
    k_attn<<<dim3(BH, NS), 256, ATTN_SMEM>>>(keys, vals);
    k_fill<<<dim3(BH, LQ / 128), 256>>>(out);
    k_combine<<<BH, 256>>>(out);
}